// round 1
// baseline (speedup 1.0000x reference)
#include <cuda_runtime.h>
#include <math.h>

// Problem constants
#define BB   2
#define SEQ  2048
#define DM   1024
#define HH   16
#define DHD  64

// Scratch: Q,K,V in [B,H,S,DH] layout; AO in [B,S,D] layout
__device__ float g_Q [BB*HH*SEQ*DHD];
__device__ float g_K [BB*HH*SEQ*DHD];
__device__ float g_V [BB*HH*SEQ*DHD];
__device__ float g_AO[BB*SEQ*DM];

// ---------------------------------------------------------------------------
// SGEMM: C[M,N] = A[M,K] @ W[K,N] + bias,  M=4096, N=1024, K=1024 (all fixed)
// 128x128 block tile, BK=16, 256 threads, 8x8 register microtile.
// splitHeads=1: write C in head-split [B,H,S,DH] layout.
// ---------------------------------------------------------------------------
constexpr int GM = 4096, GN = 1024, GK = 1024;
constexpr int TBM = 128, TBN = 128, TBK = 16;

__global__ __launch_bounds__(256)
void sgemm_kernel(const float* __restrict__ A,
                  const float* __restrict__ W,
                  const float* __restrict__ bias,
                  float* __restrict__ C,
                  int splitHeads)
{
    __shared__ __align__(16) float As[TBK * TBM];   // [k][m] (transposed)
    __shared__ __align__(16) float Bs[TBK * TBN];   // [k][n]

    const int tid = threadIdx.x;
    const int tr  = tid >> 4;     // 0..15 -> row group
    const int tc  = tid & 15;     // 0..15 -> col group
    const int mBase = blockIdx.y * TBM;
    const int nBase = blockIdx.x * TBN;

    float acc[8][8];
#pragma unroll
    for (int i = 0; i < 8; i++)
#pragma unroll
        for (int j = 0; j < 8; j++) acc[i][j] = 0.0f;

    for (int k0 = 0; k0 < GK; k0 += TBK) {
        // Load A tile 128x16 (512 float4, 2 per thread), store transposed
#pragma unroll
        for (int it = 0; it < 2; it++) {
            int id = tid + it * 256;          // 0..511
            int r  = id >> 2;                 // 0..127
            int c4 = id & 3;                  // 0..3 (float4 within 16)
            float4 v = *reinterpret_cast<const float4*>(
                A + (size_t)(mBase + r) * GK + k0 + c4 * 4);
            As[(c4 * 4 + 0) * TBM + r] = v.x;
            As[(c4 * 4 + 1) * TBM + r] = v.y;
            As[(c4 * 4 + 2) * TBM + r] = v.z;
            As[(c4 * 4 + 3) * TBM + r] = v.w;
        }
        // Load W tile 16x128 (512 float4, 2 per thread), direct
#pragma unroll
        for (int it = 0; it < 2; it++) {
            int id = tid + it * 256;
            int kk = id >> 5;                 // 0..15
            int c4 = id & 31;                 // 0..31
            *reinterpret_cast<float4*>(&Bs[kk * TBN + c4 * 4]) =
                *reinterpret_cast<const float4*>(
                    W + (size_t)(k0 + kk) * GN + nBase + c4 * 4);
        }
        __syncthreads();

#pragma unroll
        for (int kk = 0; kk < TBK; kk++) {
            float a[8], b[8];
            *reinterpret_cast<float4*>(&a[0]) =
                *reinterpret_cast<const float4*>(&As[kk * TBM + tr * 8]);
            *reinterpret_cast<float4*>(&a[4]) =
                *reinterpret_cast<const float4*>(&As[kk * TBM + tr * 8 + 4]);
            *reinterpret_cast<float4*>(&b[0]) =
                *reinterpret_cast<const float4*>(&Bs[kk * TBN + tc * 8]);
            *reinterpret_cast<float4*>(&b[4]) =
                *reinterpret_cast<const float4*>(&Bs[kk * TBN + tc * 8 + 4]);
#pragma unroll
            for (int i = 0; i < 8; i++)
#pragma unroll
                for (int j = 0; j < 8; j++)
                    acc[i][j] = fmaf(a[i], b[j], acc[i][j]);
        }
        __syncthreads();
    }

    // Epilogue
#pragma unroll
    for (int i = 0; i < 8; i++) {
        int row = mBase + tr * 8 + i;
#pragma unroll
        for (int j = 0; j < 8; j++) {
            int col = nBase + tc * 8 + j;
            float v = acc[i][j] + bias[col];
            if (splitHeads) {
                int b  = row >> 11;           // row / SEQ
                int s  = row & (SEQ - 1);
                int h  = col >> 6;            // col / DHD
                int dh = col & (DHD - 1);
                C[(((size_t)(b * HH + h) * SEQ + s) * DHD) + dh] = v;
            } else {
                C[(size_t)row * GN + col] = v;
            }
        }
    }
}

// ---------------------------------------------------------------------------
// Flash-attention: one CTA = 64 queries of one (b,h); online softmax over
// key tiles of 64. 256 threads, 4x4 scores/output per thread.
// Column mapping: thread (tr,tc) owns rows 4*tr+i, cols tc+16*j
// (strided cols -> conflict-free LDS with PAD=65).
// ---------------------------------------------------------------------------
constexpr int APAD = 65;
constexpr int ATTN_SMEM = 4 * 64 * APAD * (int)sizeof(float);  // 66560 B

__global__ __launch_bounds__(256)
void attn_kernel(const float* __restrict__ Q,
                 const float* __restrict__ K,
                 const float* __restrict__ V,
                 float* __restrict__ AO)
{
    extern __shared__ float sm[];
    float* sQ = sm;                  // [64][APAD]
    float* sK = sQ + 64 * APAD;
    float* sV = sK + 64 * APAD;
    float* sP = sV + 64 * APAD;

    const int tid = threadIdx.x;
    const int bh  = blockIdx.y;              // b*HH + h
    const int q0  = blockIdx.x * 64;

    const float* Qb = Q + ((size_t)bh * SEQ + q0) * DHD;
    const float* Kb = K + (size_t)bh * SEQ * DHD;
    const float* Vb = V + (size_t)bh * SEQ * DHD;

    // Load Q tile, pre-scaled by 1/sqrt(DH)
    for (int i = tid; i < 64 * 64; i += 256) {
        int r = i >> 6, c = i & 63;
        sQ[r * APAD + c] = Qb[i] * 0.125f;
    }

    const int tr = tid >> 4;     // 0..15
    const int tc = tid & 15;     // 0..15

    float o[4][4];
    float m_i[4], l_i[4];
#pragma unroll
    for (int i = 0; i < 4; i++) {
        m_i[i] = -1e30f; l_i[i] = 0.0f;
#pragma unroll
        for (int j = 0; j < 4; j++) o[i][j] = 0.0f;
    }

    for (int kt = 0; kt < SEQ; kt += 64) {
        // Load K & V tiles
        for (int i = tid; i < 64 * 64; i += 256) {
            int r = i >> 6, c = i & 63;
            sK[r * APAD + c] = Kb[(size_t)kt * DHD + i];
            sV[r * APAD + c] = Vb[(size_t)kt * DHD + i];
        }
        __syncthreads();

        // S = Q @ K^T  (scaled)
        float s[4][4];
#pragma unroll
        for (int i = 0; i < 4; i++)
#pragma unroll
            for (int j = 0; j < 4; j++) s[i][j] = 0.0f;

#pragma unroll 8
        for (int k = 0; k < 64; k++) {
            float a[4], b[4];
#pragma unroll
            for (int i = 0; i < 4; i++) a[i] = sQ[(4 * tr + i) * APAD + k];
#pragma unroll
            for (int j = 0; j < 4; j++) b[j] = sK[(tc + 16 * j) * APAD + k];
#pragma unroll
            for (int i = 0; i < 4; i++)
#pragma unroll
                for (int j = 0; j < 4; j++)
                    s[i][j] = fmaf(a[i], b[j], s[i][j]);
        }

        // Online softmax per row (row stats replicated across the 16 tc lanes)
#pragma unroll
        for (int i = 0; i < 4; i++) {
            float mloc = fmaxf(fmaxf(s[i][0], s[i][1]), fmaxf(s[i][2], s[i][3]));
#pragma unroll
            for (int off = 8; off >= 1; off >>= 1)
                mloc = fmaxf(mloc, __shfl_xor_sync(0xffffffffu, mloc, off));
            float mnew = fmaxf(m_i[i], mloc);
            float sc   = __expf(m_i[i] - mnew);
            m_i[i] = mnew;
            float ssum = 0.0f;
#pragma unroll
            for (int j = 0; j < 4; j++) {
                float p = __expf(s[i][j] - mnew);
                s[i][j] = p;
                ssum += p;
            }
#pragma unroll
            for (int off = 8; off >= 1; off >>= 1)
                ssum += __shfl_xor_sync(0xffffffffu, ssum, off);
            l_i[i] = l_i[i] * sc + ssum;
#pragma unroll
            for (int j = 0; j < 4; j++) {
                o[i][j] *= sc;
                sP[(4 * tr + i) * APAD + tc + 16 * j] = s[i][j];
            }
        }
        __syncthreads();

        // O += P @ V
#pragma unroll 8
        for (int k = 0; k < 64; k++) {
            float a[4], b[4];
#pragma unroll
            for (int i = 0; i < 4; i++) a[i] = sP[(4 * tr + i) * APAD + k];
#pragma unroll
            for (int j = 0; j < 4; j++) b[j] = sV[k * APAD + tc + 16 * j];
#pragma unroll
            for (int i = 0; i < 4; i++)
#pragma unroll
                for (int j = 0; j < 4; j++)
                    o[i][j] = fmaf(a[i], b[j], o[i][j]);
        }
        __syncthreads();
    }

    // Write normalized output in [B,S,D] layout (merge heads in-place)
    const int b = bh >> 4;
    const int h = bh & 15;
#pragma unroll
    for (int i = 0; i < 4; i++) {
        int q = q0 + 4 * tr + i;
        float inv = 1.0f / l_i[i];
#pragma unroll
        for (int j = 0; j < 4; j++) {
            int dh = tc + 16 * j;
            AO[((size_t)(b * SEQ + q)) * DM + h * DHD + dh] = o[i][j] * inv;
        }
    }
}

// ---------------------------------------------------------------------------
// Launch
// ---------------------------------------------------------------------------
extern "C" void kernel_launch(void* const* d_in, const int* in_sizes, int n_in,
                              void* d_out, int out_size)
{
    const float* x  = (const float*)d_in[0];
    const float* Wq = (const float*)d_in[1];
    const float* bq = (const float*)d_in[2];
    const float* Wk = (const float*)d_in[3];
    const float* bk = (const float*)d_in[4];
    const float* Wv = (const float*)d_in[5];
    const float* bv = (const float*)d_in[6];
    const float* Wo = (const float*)d_in[7];
    const float* bo = (const float*)d_in[8];

    float *Qp, *Kp, *Vp, *AOp;
    cudaGetSymbolAddress((void**)&Qp,  g_Q);
    cudaGetSymbolAddress((void**)&Kp,  g_K);
    cudaGetSymbolAddress((void**)&Vp,  g_V);
    cudaGetSymbolAddress((void**)&AOp, g_AO);

    cudaFuncSetAttribute(attn_kernel,
                         cudaFuncAttributeMaxDynamicSharedMemorySize,
                         ATTN_SMEM);

    dim3 gGemm(GN / TBN, GM / TBM);   // (8, 32)

    sgemm_kernel<<<gGemm, 256>>>(x, Wq, bq, Qp, 1);
    sgemm_kernel<<<gGemm, 256>>>(x, Wk, bk, Kp, 1);
    sgemm_kernel<<<gGemm, 256>>>(x, Wv, bv, Vp, 1);

    attn_kernel<<<dim3(SEQ / 64, BB * HH), 256, ATTN_SMEM>>>(Qp, Kp, Vp, AOp);

    sgemm_kernel<<<gGemm, 256>>>(AOp, Wo, bo, (float*)d_out, 0);
}

// round 3
// speedup vs baseline: 1.2406x; 1.2406x over previous
#include <cuda_runtime.h>
#include <cuda_bf16.h>
#include <math.h>
#include <stdint.h>

// Problem constants
#define BB   2
#define SEQ  2048
#define DM   1024
#define HH   16
#define DHD  64

// Scratch
__device__ float g_Q [BB*HH*SEQ*DHD];
__device__ float g_K [BB*HH*SEQ*DHD];
__device__ float g_V [BB*HH*SEQ*DHD];
__device__ float g_AO[BB*SEQ*DM];

// ---------------------------------------------------------------------------
// mma.sync helpers (sm_80+ path; tcgen05 unavailable at the harness's sm_103
// target)
// ---------------------------------------------------------------------------
__device__ __forceinline__ uint32_t smem_u32(const void* p) {
    uint32_t a;
    asm("{ .reg .u64 t; cvta.to.shared.u64 t, %1; cvt.u32.u64 %0, t; }"
        : "=r"(a) : "l"(p));
    return a;
}

__device__ __forceinline__ void ldm4(uint32_t* r, uint32_t addr) {
    asm volatile("ldmatrix.sync.aligned.m8n8.x4.shared.b16 {%0,%1,%2,%3}, [%4];"
        : "=r"(r[0]), "=r"(r[1]), "=r"(r[2]), "=r"(r[3]) : "r"(addr));
}

__device__ __forceinline__ void mma16816(float* c, const uint32_t* a,
                                         const uint32_t* b) {
    asm volatile(
        "mma.sync.aligned.m16n8k16.row.col.f32.bf16.bf16.f32 "
        "{%0,%1,%2,%3}, {%4,%5,%6,%7}, {%8,%9}, {%0,%1,%2,%3};"
        : "+f"(c[0]), "+f"(c[1]), "+f"(c[2]), "+f"(c[3])
        : "r"(a[0]), "r"(a[1]), "r"(a[2]), "r"(a[3]), "r"(b[0]), "r"(b[1]));
}

// ---------------------------------------------------------------------------
// bf16x3 split-precision GEMM via mma.sync.
// C[M,N] = A[M,K] @ W[K,N] + bias;  M=4096, N=1024, K=1024.
// CTA tile 128x128, BK=32, 8 warps, warp tile 64x32.
// ---------------------------------------------------------------------------
constexpr int GM = 4096, GN = 1024, GK = 1024;
constexpr int BK = 32;
constexpr int AST = 40;   // smem row stride in bf16 elems (80B -> conflict-free ldmatrix)

__global__ __launch_bounds__(256, 1)
void gemm_mma(const float* __restrict__ A,
              const float* __restrict__ W,
              const float* __restrict__ bias,
              float* __restrict__ C,
              int splitHeads)
{
    __shared__ __align__(16) __nv_bfloat16 sAh[128 * AST];
    __shared__ __align__(16) __nv_bfloat16 sAl[128 * AST];
    __shared__ __align__(16) __nv_bfloat16 sBh[128 * AST];
    __shared__ __align__(16) __nv_bfloat16 sBl[128 * AST];

    const int tid  = threadIdx.x;
    const int wid  = tid >> 5;
    const int lane = tid & 31;
    const int wm   = wid & 1;        // 0..1 : 64-row slab
    const int wn   = wid >> 1;       // 0..3 : 32-col slab
    const int mBase = blockIdx.y * 128;
    const int nBase = blockIdx.x * 128;

    const uint32_t uAh = smem_u32(sAh);
    const uint32_t uAl = smem_u32(sAl);
    const uint32_t uBh = smem_u32(sBh);
    const uint32_t uBl = smem_u32(sBl);

    float acc[4][4][4];
#pragma unroll
    for (int i = 0; i < 4; i++)
#pragma unroll
        for (int j = 0; j < 4; j++)
#pragma unroll
            for (int q = 0; q < 4; q++) acc[i][j][q] = 0.0f;

    // Precomputed ldmatrix lane addressing
    // A (m16xk16 block): matrices (m0-7,k0-7)(m8-15,k0-7)(m0-7,k8-15)(m8-15,k8-15)
    const int aRow = wm * 64 + ((lane >> 3) & 1) * 8 + (lane & 7);  // + mb*16
    const int aKel = (lane >> 4) * 8;                                // + ks*16
    // B (two n8 blocks x k16): matrices (nb,k0-7)(nb,k8-15)(nb+1,k0-7)(nb+1,k8-15)
    const int bRow = wn * 32 + (lane >> 4) * 8 + (lane & 7);         // + nbp*16
    const int bKel = ((lane >> 3) & 1) * 8;                          // + ks*16

    for (int k0 = 0; k0 < GK; k0 += BK) {
        // ---- Stage A[128][32] fp32 -> hi/lo bf16, row-major [m][k] ----
#pragma unroll
        for (int it = 0; it < 4; it++) {
            int id = tid + it * 256;          // 0..1023 float4s
            int r  = id >> 3;                 // 0..127
            int c4 = id & 7;                  // k = c4*4
            float4 v = *reinterpret_cast<const float4*>(
                A + (size_t)(mBase + r) * GK + k0 + c4 * 4);
            __nv_bfloat162 h0 = __floats2bfloat162_rn(v.x, v.y);
            __nv_bfloat162 h1 = __floats2bfloat162_rn(v.z, v.w);
            __nv_bfloat162 l0 = __floats2bfloat162_rn(
                v.x - __bfloat162float(h0.x), v.y - __bfloat162float(h0.y));
            __nv_bfloat162 l1 = __floats2bfloat162_rn(
                v.z - __bfloat162float(h1.x), v.w - __bfloat162float(h1.y));
            int sb = r * AST + c4 * 4;
            *reinterpret_cast<__nv_bfloat162*>(&sAh[sb])     = h0;
            *reinterpret_cast<__nv_bfloat162*>(&sAh[sb + 2]) = h1;
            *reinterpret_cast<__nv_bfloat162*>(&sAl[sb])     = l0;
            *reinterpret_cast<__nv_bfloat162*>(&sAl[sb + 2]) = l1;
        }

        // ---- Stage B: W[k0..k0+31][nBase..nBase+127] -> [n][k] hi/lo (2x2) ----
#pragma unroll
        for (int it = 0; it < 4; it++) {
            int id = tid + it * 256;          // 0..1023 2x2 blocks
            int kp = id >> 6;                 // 0..15 -> k = 2*kp
            int np = id & 63;                 // 0..63 -> n = 2*np
            const float* wp = W + (size_t)(k0 + 2 * kp) * GN + nBase + 2 * np;
            float2 w0 = *reinterpret_cast<const float2*>(wp);
            float2 w1 = *reinterpret_cast<const float2*>(wp + GN);
            // row n=2np holds (k,k+1); row n=2np+1 holds (k,k+1)
            __nv_bfloat162 h0 = __floats2bfloat162_rn(w0.x, w1.x);
            __nv_bfloat162 h1 = __floats2bfloat162_rn(w0.y, w1.y);
            __nv_bfloat162 l0 = __floats2bfloat162_rn(
                w0.x - __bfloat162float(h0.x), w1.x - __bfloat162float(h0.y));
            __nv_bfloat162 l1 = __floats2bfloat162_rn(
                w0.y - __bfloat162float(h1.x), w1.y - __bfloat162float(h1.y));
            int s0 = (2 * np) * AST + 2 * kp;
            int s1 = (2 * np + 1) * AST + 2 * kp;
            *reinterpret_cast<__nv_bfloat162*>(&sBh[s0]) = h0;
            *reinterpret_cast<__nv_bfloat162*>(&sBh[s1]) = h1;
            *reinterpret_cast<__nv_bfloat162*>(&sBl[s0]) = l0;
            *reinterpret_cast<__nv_bfloat162*>(&sBl[s1]) = l1;
        }
        __syncthreads();

        // ---- Compute: 2 k-steps of 16 ----
#pragma unroll
        for (int ks = 0; ks < 2; ks++) {
            uint32_t ah[4][4], al[4][4];
#pragma unroll
            for (int mb = 0; mb < 4; mb++) {
                uint32_t off = (uint32_t)((aRow + mb * 16) * AST +
                                          ks * 16 + aKel) * 2;
                ldm4(ah[mb], uAh + off);
                ldm4(al[mb], uAl + off);
            }
            uint32_t bh[4][2], bl[4][2];
#pragma unroll
            for (int nbp = 0; nbp < 2; nbp++) {
                uint32_t off = (uint32_t)((bRow + nbp * 16) * AST +
                                          ks * 16 + bKel) * 2;
                uint32_t th[4], tl[4];
                ldm4(th, uBh + off);
                ldm4(tl, uBl + off);
                bh[nbp * 2][0] = th[0]; bh[nbp * 2][1] = th[1];
                bh[nbp * 2 + 1][0] = th[2]; bh[nbp * 2 + 1][1] = th[3];
                bl[nbp * 2][0] = tl[0]; bl[nbp * 2][1] = tl[1];
                bl[nbp * 2 + 1][0] = tl[2]; bl[nbp * 2 + 1][1] = tl[3];
            }
#pragma unroll
            for (int mb = 0; mb < 4; mb++)
#pragma unroll
                for (int nb = 0; nb < 4; nb++) {
                    mma16816(acc[mb][nb], ah[mb], bh[nb]);
                    mma16816(acc[mb][nb], ah[mb], bl[nb]);
                    mma16816(acc[mb][nb], al[mb], bh[nb]);
                }
        }
        __syncthreads();
    }

    // ---- Epilogue ----
    const int gid = lane >> 2;
    const int tig = lane & 3;
#pragma unroll
    for (int nb = 0; nb < 4; nb++) {
        int col = nBase + wn * 32 + nb * 8 + 2 * tig;
        float2 bv = *reinterpret_cast<const float2*>(bias + col);
#pragma unroll
        for (int mb = 0; mb < 4; mb++) {
            int row0 = mBase + wm * 64 + mb * 16 + gid;
#pragma unroll
            for (int half = 0; half < 2; half++) {
                int row = row0 + half * 8;
                float2 o;
                o.x = acc[mb][nb][half * 2 + 0] + bv.x;
                o.y = acc[mb][nb][half * 2 + 1] + bv.y;
                if (splitHeads) {
                    int b = row >> 11, s = row & (SEQ - 1);
                    int h = col >> 6, dh = col & (DHD - 1);
                    *reinterpret_cast<float2*>(
                        &C[(((size_t)(b * HH + h) * SEQ + s) * DHD) + dh]) = o;
                } else {
                    *reinterpret_cast<float2*>(&C[(size_t)row * GN + col]) = o;
                }
            }
        }
    }
}

// ---------------------------------------------------------------------------
// Flash-attention (unchanged from R1)
// ---------------------------------------------------------------------------
constexpr int APAD = 65;
constexpr int ATTN_SMEM = 4 * 64 * APAD * (int)sizeof(float);  // 66560 B

__global__ __launch_bounds__(256)
void attn_kernel(const float* __restrict__ Q,
                 const float* __restrict__ K,
                 const float* __restrict__ V,
                 float* __restrict__ AO)
{
    extern __shared__ float sm[];
    float* sQ = sm;
    float* sK = sQ + 64 * APAD;
    float* sV = sK + 64 * APAD;
    float* sP = sV + 64 * APAD;

    const int tid = threadIdx.x;
    const int bh  = blockIdx.y;
    const int q0  = blockIdx.x * 64;

    const float* Qb = Q + ((size_t)bh * SEQ + q0) * DHD;
    const float* Kb = K + (size_t)bh * SEQ * DHD;
    const float* Vb = V + (size_t)bh * SEQ * DHD;

    for (int i = tid; i < 64 * 64; i += 256) {
        int r = i >> 6, c = i & 63;
        sQ[r * APAD + c] = Qb[i] * 0.125f;
    }

    const int tr = tid >> 4;
    const int tc = tid & 15;

    float o[4][4];
    float m_i[4], l_i[4];
#pragma unroll
    for (int i = 0; i < 4; i++) {
        m_i[i] = -1e30f; l_i[i] = 0.0f;
#pragma unroll
        for (int j = 0; j < 4; j++) o[i][j] = 0.0f;
    }

    for (int kt = 0; kt < SEQ; kt += 64) {
        for (int i = tid; i < 64 * 64; i += 256) {
            int r = i >> 6, c = i & 63;
            sK[r * APAD + c] = Kb[(size_t)kt * DHD + i];
            sV[r * APAD + c] = Vb[(size_t)kt * DHD + i];
        }
        __syncthreads();

        float s[4][4];
#pragma unroll
        for (int i = 0; i < 4; i++)
#pragma unroll
            for (int j = 0; j < 4; j++) s[i][j] = 0.0f;

#pragma unroll 8
        for (int k = 0; k < 64; k++) {
            float a[4], b[4];
#pragma unroll
            for (int i = 0; i < 4; i++) a[i] = sQ[(4 * tr + i) * APAD + k];
#pragma unroll
            for (int j = 0; j < 4; j++) b[j] = sK[(tc + 16 * j) * APAD + k];
#pragma unroll
            for (int i = 0; i < 4; i++)
#pragma unroll
                for (int j = 0; j < 4; j++)
                    s[i][j] = fmaf(a[i], b[j], s[i][j]);
        }

#pragma unroll
        for (int i = 0; i < 4; i++) {
            float mloc = fmaxf(fmaxf(s[i][0], s[i][1]), fmaxf(s[i][2], s[i][3]));
#pragma unroll
            for (int off = 8; off >= 1; off >>= 1)
                mloc = fmaxf(mloc, __shfl_xor_sync(0xffffffffu, mloc, off));
            float mnew = fmaxf(m_i[i], mloc);
            float sc   = __expf(m_i[i] - mnew);
            m_i[i] = mnew;
            float ssum = 0.0f;
#pragma unroll
            for (int j = 0; j < 4; j++) {
                float p = __expf(s[i][j] - mnew);
                s[i][j] = p;
                ssum += p;
            }
#pragma unroll
            for (int off = 8; off >= 1; off >>= 1)
                ssum += __shfl_xor_sync(0xffffffffu, ssum, off);
            l_i[i] = l_i[i] * sc + ssum;
#pragma unroll
            for (int j = 0; j < 4; j++) {
                o[i][j] *= sc;
                sP[(4 * tr + i) * APAD + tc + 16 * j] = s[i][j];
            }
        }
        __syncthreads();

#pragma unroll 8
        for (int k = 0; k < 64; k++) {
            float a[4], b[4];
#pragma unroll
            for (int i = 0; i < 4; i++) a[i] = sP[(4 * tr + i) * APAD + k];
#pragma unroll
            for (int j = 0; j < 4; j++) b[j] = sV[k * APAD + tc + 16 * j];
#pragma unroll
            for (int i = 0; i < 4; i++)
#pragma unroll
                for (int j = 0; j < 4; j++)
                    o[i][j] = fmaf(a[i], b[j], o[i][j]);
        }
        __syncthreads();
    }

    const int b = bh >> 4;
    const int h = bh & 15;
#pragma unroll
    for (int i = 0; i < 4; i++) {
        int q = q0 + 4 * tr + i;
        float inv = 1.0f / l_i[i];
#pragma unroll
        for (int j = 0; j < 4; j++) {
            int dh = tc + 16 * j;
            AO[((size_t)(b * SEQ + q)) * DM + h * DHD + dh] = o[i][j] * inv;
        }
    }
}

// ---------------------------------------------------------------------------
// Launch
// ---------------------------------------------------------------------------
extern "C" void kernel_launch(void* const* d_in, const int* in_sizes, int n_in,
                              void* d_out, int out_size)
{
    const float* x  = (const float*)d_in[0];
    const float* Wq = (const float*)d_in[1];
    const float* bq = (const float*)d_in[2];
    const float* Wk = (const float*)d_in[3];
    const float* bk = (const float*)d_in[4];
    const float* Wv = (const float*)d_in[5];
    const float* bv = (const float*)d_in[6];
    const float* Wo = (const float*)d_in[7];
    const float* bo = (const float*)d_in[8];

    float *Qp, *Kp, *Vp, *AOp;
    cudaGetSymbolAddress((void**)&Qp,  g_Q);
    cudaGetSymbolAddress((void**)&Kp,  g_K);
    cudaGetSymbolAddress((void**)&Vp,  g_V);
    cudaGetSymbolAddress((void**)&AOp, g_AO);

    cudaFuncSetAttribute(attn_kernel,
                         cudaFuncAttributeMaxDynamicSharedMemorySize, ATTN_SMEM);

    dim3 gGemm(GN / 128, GM / 128);   // (8, 32)

    gemm_mma<<<gGemm, 256>>>(x, Wq, bq, Qp, 1);
    gemm_mma<<<gGemm, 256>>>(x, Wk, bk, Kp, 1);
    gemm_mma<<<gGemm, 256>>>(x, Wv, bv, Vp, 1);

    attn_kernel<<<dim3(SEQ / 64, BB * HH), 256, ATTN_SMEM>>>(Qp, Kp, Vp, AOp);

    gemm_mma<<<gGemm, 256>>>(AOp, Wo, bo, (float*)d_out, 0);
}

// round 4
// speedup vs baseline: 1.9223x; 1.5496x over previous
#include <cuda_runtime.h>
#include <cuda_bf16.h>
#include <math.h>
#include <stdint.h>

// Problem constants
#define BB   2
#define SEQ  2048
#define DM   1024
#define HH   16
#define DHD  64

// Scratch: Q/K/V as split-precision bf16 hi/lo pairs, [B,H,S,DH] layout
__device__ __nv_bfloat16 g_Qh[BB*HH*SEQ*DHD];
__device__ __nv_bfloat16 g_Ql[BB*HH*SEQ*DHD];
__device__ __nv_bfloat16 g_Kh[BB*HH*SEQ*DHD];
__device__ __nv_bfloat16 g_Kl[BB*HH*SEQ*DHD];
__device__ __nv_bfloat16 g_Vh[BB*HH*SEQ*DHD];
__device__ __nv_bfloat16 g_Vl[BB*HH*SEQ*DHD];
__device__ float g_AO[BB*SEQ*DM];

// ---------------------------------------------------------------------------
// mma.sync helpers (sm_80+ path; tcgen05 unavailable at plain sm_103 target)
// ---------------------------------------------------------------------------
__device__ __forceinline__ uint32_t smem_u32(const void* p) {
    uint32_t a;
    asm("{ .reg .u64 t; cvta.to.shared.u64 t, %1; cvt.u32.u64 %0, t; }"
        : "=r"(a) : "l"(p));
    return a;
}

__device__ __forceinline__ void ldm4(uint32_t* r, uint32_t addr) {
    asm volatile("ldmatrix.sync.aligned.m8n8.x4.shared.b16 {%0,%1,%2,%3}, [%4];"
        : "=r"(r[0]), "=r"(r[1]), "=r"(r[2]), "=r"(r[3]) : "r"(addr));
}

__device__ __forceinline__ void mma16816(float* c, const uint32_t* a,
                                         const uint32_t* b) {
    asm volatile(
        "mma.sync.aligned.m16n8k16.row.col.f32.bf16.bf16.f32 "
        "{%0,%1,%2,%3}, {%4,%5,%6,%7}, {%8,%9}, {%0,%1,%2,%3};"
        : "+f"(c[0]), "+f"(c[1]), "+f"(c[2]), "+f"(c[3])
        : "r"(a[0]), "r"(a[1]), "r"(a[2]), "r"(a[3]), "r"(b[0]), "r"(b[1]));
}

// split (x,y) fp32 -> packed bf16 hi pair + lo (residual) pair
__device__ __forceinline__ void split2(float x, float y,
                                       uint32_t& h, uint32_t& l) {
    __nv_bfloat162 hh = __floats2bfloat162_rn(x, y);
    __nv_bfloat162 ll = __floats2bfloat162_rn(x - __bfloat162float(hh.x),
                                              y - __bfloat162float(hh.y));
    h = *reinterpret_cast<uint32_t*>(&hh);
    l = *reinterpret_cast<uint32_t*>(&ll);
}

// ---------------------------------------------------------------------------
// bf16x3 split-precision GEMM via mma.sync.
// C[M,N] = (A[M,K] @ W[K,N] + bias) * scale;  M=4096, N=1024, K=1024.
// splitHeads: write hi/lo bf16 pairs in [B,H,S,DH] layout; else fp32 [M,N].
// ---------------------------------------------------------------------------
constexpr int GM = 4096, GN = 1024, GK = 1024;
constexpr int BK = 32;
constexpr int AST = 40;

__global__ __launch_bounds__(256, 1)
void gemm_mma(const float* __restrict__ A,
              const float* __restrict__ W,
              const float* __restrict__ bias,
              float* __restrict__ C,
              __nv_bfloat16* __restrict__ Ch,
              __nv_bfloat16* __restrict__ Cl,
              float scale,
              int splitHeads)
{
    __shared__ __align__(16) __nv_bfloat16 sAh[128 * AST];
    __shared__ __align__(16) __nv_bfloat16 sAl[128 * AST];
    __shared__ __align__(16) __nv_bfloat16 sBh[128 * AST];
    __shared__ __align__(16) __nv_bfloat16 sBl[128 * AST];

    const int tid  = threadIdx.x;
    const int wid  = tid >> 5;
    const int lane = tid & 31;
    const int wm   = wid & 1;
    const int wn   = wid >> 1;
    const int mBase = blockIdx.y * 128;
    const int nBase = blockIdx.x * 128;

    const uint32_t uAh = smem_u32(sAh);
    const uint32_t uAl = smem_u32(sAl);
    const uint32_t uBh = smem_u32(sBh);
    const uint32_t uBl = smem_u32(sBl);

    float acc[4][4][4];
#pragma unroll
    for (int i = 0; i < 4; i++)
#pragma unroll
        for (int j = 0; j < 4; j++)
#pragma unroll
            for (int q = 0; q < 4; q++) acc[i][j][q] = 0.0f;

    const int aRow = wm * 64 + ((lane >> 3) & 1) * 8 + (lane & 7);
    const int aKel = (lane >> 4) * 8;
    const int bRow = wn * 32 + (lane >> 4) * 8 + (lane & 7);
    const int bKel = ((lane >> 3) & 1) * 8;

    for (int k0 = 0; k0 < GK; k0 += BK) {
#pragma unroll
        for (int it = 0; it < 4; it++) {
            int id = tid + it * 256;
            int r  = id >> 3;
            int c4 = id & 7;
            float4 v = *reinterpret_cast<const float4*>(
                A + (size_t)(mBase + r) * GK + k0 + c4 * 4);
            __nv_bfloat162 h0 = __floats2bfloat162_rn(v.x, v.y);
            __nv_bfloat162 h1 = __floats2bfloat162_rn(v.z, v.w);
            __nv_bfloat162 l0 = __floats2bfloat162_rn(
                v.x - __bfloat162float(h0.x), v.y - __bfloat162float(h0.y));
            __nv_bfloat162 l1 = __floats2bfloat162_rn(
                v.z - __bfloat162float(h1.x), v.w - __bfloat162float(h1.y));
            int sb = r * AST + c4 * 4;
            *reinterpret_cast<__nv_bfloat162*>(&sAh[sb])     = h0;
            *reinterpret_cast<__nv_bfloat162*>(&sAh[sb + 2]) = h1;
            *reinterpret_cast<__nv_bfloat162*>(&sAl[sb])     = l0;
            *reinterpret_cast<__nv_bfloat162*>(&sAl[sb + 2]) = l1;
        }
#pragma unroll
        for (int it = 0; it < 4; it++) {
            int id = tid + it * 256;
            int kp = id >> 6;
            int np = id & 63;
            const float* wp = W + (size_t)(k0 + 2 * kp) * GN + nBase + 2 * np;
            float2 w0 = *reinterpret_cast<const float2*>(wp);
            float2 w1 = *reinterpret_cast<const float2*>(wp + GN);
            __nv_bfloat162 h0 = __floats2bfloat162_rn(w0.x, w1.x);
            __nv_bfloat162 h1 = __floats2bfloat162_rn(w0.y, w1.y);
            __nv_bfloat162 l0 = __floats2bfloat162_rn(
                w0.x - __bfloat162float(h0.x), w1.x - __bfloat162float(h0.y));
            __nv_bfloat162 l1 = __floats2bfloat162_rn(
                w0.y - __bfloat162float(h1.x), w1.y - __bfloat162float(h1.y));
            int s0 = (2 * np) * AST + 2 * kp;
            int s1 = (2 * np + 1) * AST + 2 * kp;
            *reinterpret_cast<__nv_bfloat162*>(&sBh[s0]) = h0;
            *reinterpret_cast<__nv_bfloat162*>(&sBh[s1]) = h1;
            *reinterpret_cast<__nv_bfloat162*>(&sBl[s0]) = l0;
            *reinterpret_cast<__nv_bfloat162*>(&sBl[s1]) = l1;
        }
        __syncthreads();

#pragma unroll
        for (int ks = 0; ks < 2; ks++) {
            uint32_t ah[4][4], al[4][4];
#pragma unroll
            for (int mb = 0; mb < 4; mb++) {
                uint32_t off = (uint32_t)((aRow + mb * 16) * AST +
                                          ks * 16 + aKel) * 2;
                ldm4(ah[mb], uAh + off);
                ldm4(al[mb], uAl + off);
            }
            uint32_t bh[4][2], bl[4][2];
#pragma unroll
            for (int nbp = 0; nbp < 2; nbp++) {
                uint32_t off = (uint32_t)((bRow + nbp * 16) * AST +
                                          ks * 16 + bKel) * 2;
                uint32_t th[4], tl[4];
                ldm4(th, uBh + off);
                ldm4(tl, uBl + off);
                bh[nbp * 2][0] = th[0]; bh[nbp * 2][1] = th[1];
                bh[nbp * 2 + 1][0] = th[2]; bh[nbp * 2 + 1][1] = th[3];
                bl[nbp * 2][0] = tl[0]; bl[nbp * 2][1] = tl[1];
                bl[nbp * 2 + 1][0] = tl[2]; bl[nbp * 2 + 1][1] = tl[3];
            }
#pragma unroll
            for (int mb = 0; mb < 4; mb++)
#pragma unroll
                for (int nb = 0; nb < 4; nb++) {
                    mma16816(acc[mb][nb], ah[mb], bh[nb]);
                    mma16816(acc[mb][nb], ah[mb], bl[nb]);
                    mma16816(acc[mb][nb], al[mb], bh[nb]);
                }
        }
        __syncthreads();
    }

    const int gid = lane >> 2;
    const int tig = lane & 3;
#pragma unroll
    for (int nb = 0; nb < 4; nb++) {
        int col = nBase + wn * 32 + nb * 8 + 2 * tig;
        float2 bv = *reinterpret_cast<const float2*>(bias + col);
#pragma unroll
        for (int mb = 0; mb < 4; mb++) {
            int row0 = mBase + wm * 64 + mb * 16 + gid;
#pragma unroll
            for (int half = 0; half < 2; half++) {
                int row = row0 + half * 8;
                float ox = (acc[mb][nb][half * 2 + 0] + bv.x) * scale;
                float oy = (acc[mb][nb][half * 2 + 1] + bv.y) * scale;
                if (splitHeads) {
                    int b = row >> 11, s = row & (SEQ - 1);
                    int h = col >> 6, dh = col & (DHD - 1);
                    size_t idx = (((size_t)(b * HH + h) * SEQ + s) * DHD) + dh;
                    uint32_t hp, lp;
                    split2(ox, oy, hp, lp);
                    *reinterpret_cast<uint32_t*>(&Ch[idx]) = hp;
                    *reinterpret_cast<uint32_t*>(&Cl[idx]) = lp;
                } else {
                    float2 o; o.x = ox; o.y = oy;
                    *reinterpret_cast<float2*>(&C[(size_t)row * GN + col]) = o;
                }
            }
        }
    }
}

// ---------------------------------------------------------------------------
// Tensor-core flash attention (bf16x3 for both QK^T and PV).
// CTA = 128 queries of one (b,h); 8 warps, each owns 16 queries x all keys.
// Key tiles of 64. Q/K/V arrive pre-split as bf16 hi/lo.
// ---------------------------------------------------------------------------
constexpr int QST = 72;   // smem row stride (bf16 elems) -> conflict-free ldmatrix

// smem byte offsets
constexpr int AQH = 0;                       // [128][QST] bf16
constexpr int AQL = AQH + 128 * QST * 2;     // 18432
constexpr int AKH = AQL + 128 * QST * 2;     // [64][QST]
constexpr int AKL = AKH + 64 * QST * 2;
constexpr int AVH = AKL + 64 * QST * 2;      // [dh=64][key=QST stride]
constexpr int AVL = AVH + 64 * QST * 2;
constexpr int ATTN_SMEM = AVL + 64 * QST * 2;  // 73728

__global__ __launch_bounds__(256, 1)
void attn_mma(const __nv_bfloat16* __restrict__ Qh,
              const __nv_bfloat16* __restrict__ Ql,
              const __nv_bfloat16* __restrict__ Kh,
              const __nv_bfloat16* __restrict__ Kl,
              const __nv_bfloat16* __restrict__ Vh,
              const __nv_bfloat16* __restrict__ Vl,
              float* __restrict__ AO)
{
    extern __shared__ __align__(16) char smem[];
    const uint32_t sb = smem_u32(smem);
    const uint32_t uQH = sb + AQH, uQL = sb + AQL;
    const uint32_t uKH = sb + AKH, uKL = sb + AKL;
    const uint32_t uVH = sb + AVH, uVL = sb + AVL;

    const int tid  = threadIdx.x;
    const int wid  = tid >> 5;
    const int lane = tid & 31;
    const int bh   = blockIdx.y;
    const int q0   = blockIdx.x * 128;

    const size_t baseQ = ((size_t)bh * SEQ + q0) * DHD;
    const size_t baseK = (size_t)bh * SEQ * DHD;

    // ---- Stage Q tile [128][64] hi/lo (pure copy; pre-scaled, pre-split) ----
#pragma unroll
    for (int it = 0; it < 4; it++) {
        int id = tid + it * 256;             // 0..1023
        int r  = id >> 3;
        int c8 = id & 7;
        *reinterpret_cast<uint4*>(smem + AQH + (r * QST + c8 * 8) * 2) =
            *reinterpret_cast<const uint4*>(Qh + baseQ + r * 64 + c8 * 8);
        *reinterpret_cast<uint4*>(smem + AQL + (r * QST + c8 * 8) * 2) =
            *reinterpret_cast<const uint4*>(Ql + baseQ + r * 64 + c8 * 8);
    }

    // ldmatrix lane addressing
    const int aRow = wid * 16 + ((lane >> 3) & 1) * 8 + (lane & 7);
    const int aK   = (lane >> 4) * 8;
    const int bRow = (lane >> 4) * 8 + (lane & 7);      // + nbp*16
    const int bK   = ((lane >> 3) & 1) * 8;
    const int gid  = lane >> 2;
    const int tig  = lane & 3;

    float oacc[8][4];
    float m_i[2], l_i[2];
#pragma unroll
    for (int nb = 0; nb < 8; nb++)
#pragma unroll
        for (int q = 0; q < 4; q++) oacc[nb][q] = 0.0f;
    m_i[0] = m_i[1] = -1e30f;
    l_i[0] = l_i[1] = 0.0f;

    for (int kt = 0; kt < SEQ; kt += 64) {
        // ---- Stage K [64][64] hi/lo ----
#pragma unroll
        for (int it = 0; it < 2; it++) {
            int id = tid + it * 256;         // 0..511
            int r  = id >> 3;
            int c8 = id & 7;
            size_t src = baseK + (size_t)(kt + r) * 64 + c8 * 8;
            *reinterpret_cast<uint4*>(smem + AKH + (r * QST + c8 * 8) * 2) =
                *reinterpret_cast<const uint4*>(Kh + src);
            *reinterpret_cast<uint4*>(smem + AKL + (r * QST + c8 * 8) * 2) =
                *reinterpret_cast<const uint4*>(Kl + src);
        }
        // ---- Stage V transposed [dh][key] hi/lo (2x2 blocks) ----
#pragma unroll
        for (int it = 0; it < 4; it++) {
            int id = tid + it * 256;         // 0..1023
            int kp = id >> 5;                // key pair 0..31
            int dp = id & 31;                // dh pair 0..31
            size_t src = baseK + (size_t)(kt + 2 * kp) * 64 + 2 * dp;
            __nv_bfloat162 a = *reinterpret_cast<const __nv_bfloat162*>(Vh + src);
            __nv_bfloat162 c = *reinterpret_cast<const __nv_bfloat162*>(Vh + src + 64);
            __nv_bfloat162 e = *reinterpret_cast<const __nv_bfloat162*>(Vl + src);
            __nv_bfloat162 f = *reinterpret_cast<const __nv_bfloat162*>(Vl + src + 64);
            __nv_bfloat162 t0; t0.x = a.x; t0.y = c.x;
            __nv_bfloat162 t1; t1.x = a.y; t1.y = c.y;
            __nv_bfloat162 t2; t2.x = e.x; t2.y = f.x;
            __nv_bfloat162 t3; t3.x = e.y; t3.y = f.y;
            *reinterpret_cast<__nv_bfloat162*>(
                smem + AVH + ((2 * dp) * QST + 2 * kp) * 2) = t0;
            *reinterpret_cast<__nv_bfloat162*>(
                smem + AVH + ((2 * dp + 1) * QST + 2 * kp) * 2) = t1;
            *reinterpret_cast<__nv_bfloat162*>(
                smem + AVL + ((2 * dp) * QST + 2 * kp) * 2) = t2;
            *reinterpret_cast<__nv_bfloat162*>(
                smem + AVL + ((2 * dp + 1) * QST + 2 * kp) * 2) = t3;
        }
        __syncthreads();

        // ---- S = Q @ K^T (bf16x3) ----
        float sacc[8][4];
#pragma unroll
        for (int nb = 0; nb < 8; nb++)
#pragma unroll
            for (int q = 0; q < 4; q++) sacc[nb][q] = 0.0f;

#pragma unroll
        for (int ks = 0; ks < 4; ks++) {
            uint32_t ah[4], al[4];
            uint32_t qoff = (uint32_t)(aRow * QST + ks * 16 + aK) * 2;
            ldm4(ah, uQH + qoff);
            ldm4(al, uQL + qoff);
#pragma unroll
            for (int nbp = 0; nbp < 4; nbp++) {
                uint32_t koff = (uint32_t)((bRow + nbp * 16) * QST +
                                           ks * 16 + bK) * 2;
                uint32_t th[4], tl[4];
                ldm4(th, uKH + koff);
                ldm4(tl, uKL + koff);
                mma16816(sacc[2 * nbp],     ah, th);
                mma16816(sacc[2 * nbp + 1], ah, th + 2);
                mma16816(sacc[2 * nbp],     ah, tl);
                mma16816(sacc[2 * nbp + 1], ah, tl + 2);
                mma16816(sacc[2 * nbp],     al, th);
                mma16816(sacc[2 * nbp + 1], al, th + 2);
            }
        }

        // ---- Online softmax (register-resident; stats in-warp) ----
#pragma unroll
        for (int hr = 0; hr < 2; hr++) {
            float mloc = -1e30f;
#pragma unroll
            for (int nb = 0; nb < 8; nb++)
                mloc = fmaxf(mloc, fmaxf(sacc[nb][2 * hr], sacc[nb][2 * hr + 1]));
            mloc = fmaxf(mloc, __shfl_xor_sync(0xffffffffu, mloc, 1));
            mloc = fmaxf(mloc, __shfl_xor_sync(0xffffffffu, mloc, 2));
            float mnew = fmaxf(m_i[hr], mloc);
            float sc   = __expf(m_i[hr] - mnew);
            m_i[hr] = mnew;
            float ssum = 0.0f;
#pragma unroll
            for (int nb = 0; nb < 8; nb++) {
                float p0 = __expf(sacc[nb][2 * hr]     - mnew);
                float p1 = __expf(sacc[nb][2 * hr + 1] - mnew);
                sacc[nb][2 * hr]     = p0;
                sacc[nb][2 * hr + 1] = p1;
                ssum += p0 + p1;
            }
            ssum += __shfl_xor_sync(0xffffffffu, ssum, 1);
            ssum += __shfl_xor_sync(0xffffffffu, ssum, 2);
            l_i[hr] = l_i[hr] * sc + ssum;
#pragma unroll
            for (int nb = 0; nb < 8; nb++) {
                oacc[nb][2 * hr]     *= sc;
                oacc[nb][2 * hr + 1] *= sc;
            }
        }

        // ---- Pack P to bf16 hi/lo A-fragments (in registers) ----
        uint32_t ph[4][4], pl[4][4];
#pragma unroll
        for (int ks = 0; ks < 4; ks++) {
            split2(sacc[2 * ks][0],     sacc[2 * ks][1],     ph[ks][0], pl[ks][0]);
            split2(sacc[2 * ks][2],     sacc[2 * ks][3],     ph[ks][1], pl[ks][1]);
            split2(sacc[2 * ks + 1][0], sacc[2 * ks + 1][1], ph[ks][2], pl[ks][2]);
            split2(sacc[2 * ks + 1][2], sacc[2 * ks + 1][3], ph[ks][3], pl[ks][3]);
        }

        // ---- O += P @ V (bf16x3) ----
#pragma unroll
        for (int ks = 0; ks < 4; ks++) {
#pragma unroll
            for (int nbp = 0; nbp < 4; nbp++) {
                uint32_t voff = (uint32_t)((bRow + nbp * 16) * QST +
                                           ks * 16 + bK) * 2;
                uint32_t th[4], tl[4];
                ldm4(th, uVH + voff);
                ldm4(tl, uVL + voff);
                mma16816(oacc[2 * nbp],     ph[ks], th);
                mma16816(oacc[2 * nbp + 1], ph[ks], th + 2);
                mma16816(oacc[2 * nbp],     ph[ks], tl);
                mma16816(oacc[2 * nbp + 1], ph[ks], tl + 2);
                mma16816(oacc[2 * nbp],     pl[ks], th);
                mma16816(oacc[2 * nbp + 1], pl[ks], th + 2);
            }
        }
        __syncthreads();
    }

    // ---- Write normalized output, [B,S,D] layout ----
    const int b = bh >> 4;
    const int h = bh & 15;
#pragma unroll
    for (int hr = 0; hr < 2; hr++) {
        int q = q0 + wid * 16 + gid + hr * 8;
        float inv = 1.0f / l_i[hr];
        float* dst = AO + (size_t)(b * SEQ + q) * DM + h * DHD;
#pragma unroll
        for (int nb = 0; nb < 8; nb++) {
            float2 o;
            o.x = oacc[nb][2 * hr]     * inv;
            o.y = oacc[nb][2 * hr + 1] * inv;
            *reinterpret_cast<float2*>(dst + nb * 8 + 2 * tig) = o;
        }
    }
}

// ---------------------------------------------------------------------------
// Launch
// ---------------------------------------------------------------------------
extern "C" void kernel_launch(void* const* d_in, const int* in_sizes, int n_in,
                              void* d_out, int out_size)
{
    const float* x  = (const float*)d_in[0];
    const float* Wq = (const float*)d_in[1];
    const float* bq = (const float*)d_in[2];
    const float* Wk = (const float*)d_in[3];
    const float* bk = (const float*)d_in[4];
    const float* Wv = (const float*)d_in[5];
    const float* bv = (const float*)d_in[6];
    const float* Wo = (const float*)d_in[7];
    const float* bo = (const float*)d_in[8];

    __nv_bfloat16 *Qh, *Ql, *Kh, *Kl, *Vh, *Vl;
    float *AOp;
    cudaGetSymbolAddress((void**)&Qh, g_Qh);
    cudaGetSymbolAddress((void**)&Ql, g_Ql);
    cudaGetSymbolAddress((void**)&Kh, g_Kh);
    cudaGetSymbolAddress((void**)&Kl, g_Kl);
    cudaGetSymbolAddress((void**)&Vh, g_Vh);
    cudaGetSymbolAddress((void**)&Vl, g_Vl);
    cudaGetSymbolAddress((void**)&AOp, g_AO);

    cudaFuncSetAttribute(attn_mma,
                         cudaFuncAttributeMaxDynamicSharedMemorySize, ATTN_SMEM);

    dim3 gGemm(GN / 128, GM / 128);   // (8, 32)

    gemm_mma<<<gGemm, 256>>>(x, Wq, bq, nullptr, Qh, Ql, 0.125f, 1);
    gemm_mma<<<gGemm, 256>>>(x, Wk, bk, nullptr, Kh, Kl, 1.0f, 1);
    gemm_mma<<<gGemm, 256>>>(x, Wv, bv, nullptr, Vh, Vl, 1.0f, 1);

    attn_mma<<<dim3(SEQ / 128, BB * HH), 256, ATTN_SMEM>>>(
        Qh, Ql, Kh, Kl, Vh, Vl, AOp);

    gemm_mma<<<gGemm, 256>>>(AOp, Wo, bo, (float*)d_out, nullptr, nullptr,
                             1.0f, 0);
}

// round 6
// speedup vs baseline: 2.6274x; 1.3668x over previous
#include <cuda_runtime.h>
#include <cuda_bf16.h>
#include <math.h>
#include <stdint.h>

// Problem constants
#define BB   2
#define SEQ  2048
#define DM   1024
#define HH   16
#define DHD  64

// Pre-split inputs / intermediates (bf16 hi + lo residual)
__device__ __nv_bfloat16 g_xh [4096*1024];
__device__ __nv_bfloat16 g_xl [4096*1024];
__device__ __nv_bfloat16 g_Wth[4][1024*1024];   // W^T [n][k]
__device__ __nv_bfloat16 g_Wtl[4][1024*1024];
__device__ __nv_bfloat16 g_Qh[BB*HH*SEQ*DHD];
__device__ __nv_bfloat16 g_Ql[BB*HH*SEQ*DHD];
__device__ __nv_bfloat16 g_Kh[BB*HH*SEQ*DHD];
__device__ __nv_bfloat16 g_Kl[BB*HH*SEQ*DHD];
__device__ __nv_bfloat16 g_Vh[BB*HH*SEQ*DHD];
__device__ __nv_bfloat16 g_Vl[BB*HH*SEQ*DHD];
__device__ __nv_bfloat16 g_AOh[BB*SEQ*DM];
__device__ __nv_bfloat16 g_AOl[BB*SEQ*DM];

// ---------------------------------------------------------------------------
// helpers
// ---------------------------------------------------------------------------
__device__ __forceinline__ uint32_t smem_u32(const void* p) {
    uint32_t a;
    asm("{ .reg .u64 t; cvta.to.shared.u64 t, %1; cvt.u32.u64 %0, t; }"
        : "=r"(a) : "l"(p));
    return a;
}
__device__ __forceinline__ void ldm4(uint32_t* r, uint32_t addr) {
    asm volatile("ldmatrix.sync.aligned.m8n8.x4.shared.b16 {%0,%1,%2,%3}, [%4];"
        : "=r"(r[0]), "=r"(r[1]), "=r"(r[2]), "=r"(r[3]) : "r"(addr));
}
__device__ __forceinline__ void ldm4t(uint32_t* r, uint32_t addr) {
    asm volatile("ldmatrix.sync.aligned.m8n8.x4.trans.shared.b16 {%0,%1,%2,%3}, [%4];"
        : "=r"(r[0]), "=r"(r[1]), "=r"(r[2]), "=r"(r[3]) : "r"(addr));
}
__device__ __forceinline__ void mma16816(float* c, const uint32_t* a,
                                         const uint32_t* b) {
    asm volatile(
        "mma.sync.aligned.m16n8k16.row.col.f32.bf16.bf16.f32 "
        "{%0,%1,%2,%3}, {%4,%5,%6,%7}, {%8,%9}, {%0,%1,%2,%3};"
        : "+f"(c[0]), "+f"(c[1]), "+f"(c[2]), "+f"(c[3])
        : "r"(a[0]), "r"(a[1]), "r"(a[2]), "r"(a[3]), "r"(b[0]), "r"(b[1]));
}
__device__ __forceinline__ void split2(float x, float y,
                                       uint32_t& h, uint32_t& l) {
    __nv_bfloat162 hh = __floats2bfloat162_rn(x, y);
    __nv_bfloat162 ll = __floats2bfloat162_rn(x - __bfloat162float(hh.x),
                                              y - __bfloat162float(hh.y));
    h = *reinterpret_cast<uint32_t*>(&hh);
    l = *reinterpret_cast<uint32_t*>(&ll);
}

#define CPA16(dst, src) \
    asm volatile("cp.async.cg.shared.global [%0], [%1], 16;" \
                 :: "r"(dst), "l"(src))
#define CP_COMMIT() asm volatile("cp.async.commit_group;" ::: "memory")
#define CP_WAIT1()  asm volatile("cp.async.wait_group 1;" ::: "memory")
#define CP_WAIT0()  asm volatile("cp.async.wait_group 0;" ::: "memory")

// ---------------------------------------------------------------------------
// Precompute: split x (row-major [m][k]) into bf16 hi/lo
// ---------------------------------------------------------------------------
__global__ __launch_bounds__(256)
void split_x(const float* __restrict__ src,
             __nv_bfloat16* __restrict__ h,
             __nv_bfloat16* __restrict__ l)
{
    int i = blockIdx.x * 256 + threadIdx.x;   // float4 index
    float4 v = reinterpret_cast<const float4*>(src)[i];
    uint32_t h0, l0, h1, l1;
    split2(v.x, v.y, h0, l0);
    split2(v.z, v.w, h1, l1);
    uint2 hp; hp.x = h0; hp.y = h1;
    uint2 lp; lp.x = l0; lp.y = l1;
    reinterpret_cast<uint2*>(h)[i] = hp;
    reinterpret_cast<uint2*>(l)[i] = lp;
}

// ---------------------------------------------------------------------------
// Precompute: transpose W [k][n] -> [n][k] and split into bf16 hi/lo
// ---------------------------------------------------------------------------
__global__ __launch_bounds__(256)
void split_wt(const float* __restrict__ W,
              __nv_bfloat16* __restrict__ Th,
              __nv_bfloat16* __restrict__ Tl)
{
    __shared__ float t[32][33];
    const int tid = threadIdx.x;
    const int n0 = (blockIdx.x & 31) * 32;
    const int k0 = (blockIdx.x >> 5) * 32;
#pragma unroll
    for (int it = 0; it < 4; it++) {
        int id = tid + it * 256;
        int r = id >> 5, c = id & 31;
        t[r][c] = W[(size_t)(k0 + r) * 1024 + n0 + c];
    }
    __syncthreads();
    const int rn = tid >> 3;       // 0..31 n-row
    const int c4 = tid & 7;        // 0..7 group of 4 k
    uint32_t h0, l0, h1, l1;
    split2(t[c4 * 4 + 0][rn], t[c4 * 4 + 1][rn], h0, l0);
    split2(t[c4 * 4 + 2][rn], t[c4 * 4 + 3][rn], h1, l1);
    size_t o = ((size_t)(n0 + rn) * 1024 + k0 + c4 * 4) >> 1;  // uint32 units
    uint2 hp; hp.x = h0; hp.y = h1;
    uint2 lp; lp.x = l0; lp.y = l1;
    *reinterpret_cast<uint2*>(reinterpret_cast<uint32_t*>(Th) + o) = hp;
    *reinterpret_cast<uint2*>(reinterpret_cast<uint32_t*>(Tl) + o) = lp;
}

// ---------------------------------------------------------------------------
// bf16x3 GEMM, pre-split inputs, cp.async double-buffered.
// C = (Ahl @ Bthl^T + bias) * scale ; A [m][k] hi/lo, Bt [n][k] hi/lo.
// M=4096, N=1024, K=1024. CTA 128x128, BK=32, 8 warps (64x32 warp tile).
// ---------------------------------------------------------------------------
constexpr int GM = 4096, GN = 1024, GK = 1024;
constexpr int BK = 32;
constexpr int AST = 40;                         // bf16 row stride
constexpr int ARR_B   = 128 * AST * 2;          // 10240 B per array
constexpr int STAGE_B = 4 * ARR_B;              // Ah,Al,Bh,Bl
constexpr int GEMM_SMEM = 2 * STAGE_B;          // 81920 B

__global__ __launch_bounds__(256, 1)
void gemm_bf16(const __nv_bfloat16* __restrict__ Ah,
               const __nv_bfloat16* __restrict__ Al,
               const __nv_bfloat16* __restrict__ Bth,
               const __nv_bfloat16* __restrict__ Btl,
               const float* __restrict__ bias,
               float* __restrict__ C,
               __nv_bfloat16* __restrict__ Ch,
               __nv_bfloat16* __restrict__ Cl,
               float scale,
               int splitHeads)
{
    extern __shared__ __align__(16) char smem[];
    const uint32_t sb = smem_u32(smem);
    const int tid  = threadIdx.x;
    const int wid  = tid >> 5;
    const int lane = tid & 31;
    const int wm   = wid & 1;
    const int wn   = wid >> 1;
    const int mBase = blockIdx.y * 128;
    const int nBase = blockIdx.x * 128;

    // staging indices (2 x 16B per array per thread)
    const int sr0 = tid >> 2,        sc0 = (tid & 3) * 8;
    const int sr1 = (tid + 256) >> 2, sc1 = ((tid + 256) & 3) * 8;

    auto stage = [&](int st, int k0) {
        uint32_t d = sb + st * STAGE_B;
        const __nv_bfloat16* srcs[4] = {
            Ah + (size_t)(mBase + sr0) * GK + k0 + sc0,
            Al + (size_t)(mBase + sr0) * GK + k0 + sc0,
            Bth + (size_t)(nBase + sr0) * GK + k0 + sc0,
            Btl + (size_t)(nBase + sr0) * GK + k0 + sc0 };
        const __nv_bfloat16* srcs1[4] = {
            Ah + (size_t)(mBase + sr1) * GK + k0 + sc1,
            Al + (size_t)(mBase + sr1) * GK + k0 + sc1,
            Bth + (size_t)(nBase + sr1) * GK + k0 + sc1,
            Btl + (size_t)(nBase + sr1) * GK + k0 + sc1 };
        uint32_t o0 = (uint32_t)(sr0 * AST + sc0) * 2;
        uint32_t o1 = (uint32_t)(sr1 * AST + sc1) * 2;
#pragma unroll
        for (int a = 0; a < 4; a++) {
            CPA16(d + a * ARR_B + o0, srcs[a]);
            CPA16(d + a * ARR_B + o1, srcs1[a]);
        }
    };

    float acc[4][4][4];
#pragma unroll
    for (int i = 0; i < 4; i++)
#pragma unroll
        for (int j = 0; j < 4; j++)
#pragma unroll
            for (int q = 0; q < 4; q++) acc[i][j][q] = 0.0f;

    const int aRow = wm * 64 + ((lane >> 3) & 1) * 8 + (lane & 7);
    const int aKel = (lane >> 4) * 8;
    const int bRow = wn * 32 + (lane >> 4) * 8 + (lane & 7);
    const int bKel = ((lane >> 3) & 1) * 8;

    stage(0, 0);
    CP_COMMIT();

    const int NCHUNK = GK / BK;   // 32
    for (int c = 0; c < NCHUNK; c++) {
        if (c + 1 < NCHUNK) {
            stage((c + 1) & 1, (c + 1) * BK);
            CP_COMMIT();
            CP_WAIT1();
        } else {
            CP_WAIT0();
        }
        __syncthreads();

        const uint32_t base = sb + (c & 1) * STAGE_B;
        const uint32_t uAh = base, uAl = base + ARR_B;
        const uint32_t uBh = base + 2 * ARR_B, uBl = base + 3 * ARR_B;

#pragma unroll
        for (int ks = 0; ks < 2; ks++) {
            uint32_t ah[4][4], al[4][4];
#pragma unroll
            for (int mb = 0; mb < 4; mb++) {
                uint32_t off = (uint32_t)((aRow + mb * 16) * AST +
                                          ks * 16 + aKel) * 2;
                ldm4(ah[mb], uAh + off);
                ldm4(al[mb], uAl + off);
            }
            uint32_t bh[4][2], bl[4][2];
#pragma unroll
            for (int nbp = 0; nbp < 2; nbp++) {
                uint32_t off = (uint32_t)((bRow + nbp * 16) * AST +
                                          ks * 16 + bKel) * 2;
                uint32_t th[4], tl[4];
                ldm4(th, uBh + off);
                ldm4(tl, uBl + off);
                bh[nbp * 2][0] = th[0]; bh[nbp * 2][1] = th[1];
                bh[nbp * 2 + 1][0] = th[2]; bh[nbp * 2 + 1][1] = th[3];
                bl[nbp * 2][0] = tl[0]; bl[nbp * 2][1] = tl[1];
                bl[nbp * 2 + 1][0] = tl[2]; bl[nbp * 2 + 1][1] = tl[3];
            }
#pragma unroll
            for (int mb = 0; mb < 4; mb++)
#pragma unroll
                for (int nb = 0; nb < 4; nb++) {
                    mma16816(acc[mb][nb], ah[mb], bh[nb]);
                    mma16816(acc[mb][nb], ah[mb], bl[nb]);
                    mma16816(acc[mb][nb], al[mb], bh[nb]);
                }
        }
        __syncthreads();
    }

    const int gid = lane >> 2;
    const int tig = lane & 3;
#pragma unroll
    for (int nb = 0; nb < 4; nb++) {
        int col = nBase + wn * 32 + nb * 8 + 2 * tig;
        float2 bv = *reinterpret_cast<const float2*>(bias + col);
#pragma unroll
        for (int mb = 0; mb < 4; mb++) {
            int row0 = mBase + wm * 64 + mb * 16 + gid;
#pragma unroll
            for (int half = 0; half < 2; half++) {
                int row = row0 + half * 8;
                float ox = (acc[mb][nb][half * 2 + 0] + bv.x) * scale;
                float oy = (acc[mb][nb][half * 2 + 1] + bv.y) * scale;
                if (splitHeads) {
                    int b = row >> 11, s = row & (SEQ - 1);
                    int h = col >> 6, dh = col & (DHD - 1);
                    size_t idx = (((size_t)(b * HH + h) * SEQ + s) * DHD) + dh;
                    uint32_t hp, lp;
                    split2(ox, oy, hp, lp);
                    *reinterpret_cast<uint32_t*>(&Ch[idx]) = hp;
                    *reinterpret_cast<uint32_t*>(&Cl[idx]) = lp;
                } else {
                    float2 o; o.x = ox; o.y = oy;
                    *reinterpret_cast<float2*>(&C[(size_t)row * GN + col]) = o;
                }
            }
        }
    }
}

// ---------------------------------------------------------------------------
// Tensor-core flash attention, cp.async double-buffered K/V, V via
// ldmatrix.trans. CTA = 128 queries of one (b,h); 8 warps.
// Emits pre-split AO (bf16 hi/lo) for the O-projection GEMM.
// ---------------------------------------------------------------------------
constexpr int QST = 72;
constexpr int AQH = 0;                       // [128][QST]
constexpr int AQL = AQH + 128 * QST * 2;     // 18432
constexpr int KVBASE = AQL + 128 * QST * 2;  // 36864
constexpr int KARR = 64 * QST * 2;           // 9216 per array
constexpr int KVSTAGE = 4 * KARR;            // Kh,Kl,Vh,Vl
constexpr int ATTN_SMEM = KVBASE + 2 * KVSTAGE;  // 110592

__global__ __launch_bounds__(256, 1)
void attn_mma(const __nv_bfloat16* __restrict__ Qh,
              const __nv_bfloat16* __restrict__ Ql,
              const __nv_bfloat16* __restrict__ Kh,
              const __nv_bfloat16* __restrict__ Kl,
              const __nv_bfloat16* __restrict__ Vh,
              const __nv_bfloat16* __restrict__ Vl,
              __nv_bfloat16* __restrict__ AOh,
              __nv_bfloat16* __restrict__ AOl)
{
    extern __shared__ __align__(16) char smem[];
    const uint32_t sb = smem_u32(smem);
    const uint32_t uQH = sb + AQH, uQL = sb + AQL;

    const int tid  = threadIdx.x;
    const int wid  = tid >> 5;
    const int lane = tid & 31;
    const int bh   = blockIdx.y;
    const int q0   = blockIdx.x * 128;

    const size_t baseQ = ((size_t)bh * SEQ + q0) * DHD;
    const size_t baseK = (size_t)bh * SEQ * DHD;

    // K/V staging lanes: 2 x 16B per array per thread
    const int kr0 = tid >> 3,        kc0 = (tid & 7) * 8;
    const int kr1 = (tid + 256) >> 3, kc1 = ((tid + 256) & 7) * 8;

    auto stage_kv = [&](int st, int kt) {
        uint32_t d = sb + KVBASE + st * KVSTAGE;
        size_t s0 = baseK + (size_t)(kt + kr0) * DHD + kc0;
        size_t s1 = baseK + (size_t)(kt + kr1) * DHD + kc1;
        uint32_t o0 = (uint32_t)(kr0 * QST + kc0) * 2;
        uint32_t o1 = (uint32_t)(kr1 * QST + kc1) * 2;
        CPA16(d + 0 * KARR + o0, Kh + s0);
        CPA16(d + 0 * KARR + o1, Kh + s1);
        CPA16(d + 1 * KARR + o0, Kl + s0);
        CPA16(d + 1 * KARR + o1, Kl + s1);
        CPA16(d + 2 * KARR + o0, Vh + s0);
        CPA16(d + 2 * KARR + o1, Vh + s1);
        CPA16(d + 3 * KARR + o0, Vl + s0);
        CPA16(d + 3 * KARR + o1, Vl + s1);
    };

    // Q stage (cp.async, 4 x 16B per array per thread)
#pragma unroll
    for (int it = 0; it < 4; it++) {
        int id = tid + it * 256;
        int r = id >> 3, c8 = (id & 7) * 8;
        uint32_t o = (uint32_t)(r * QST + c8) * 2;
        CPA16(uQH + o, Qh + baseQ + (size_t)r * DHD + c8);
        CPA16(uQL + o, Ql + baseQ + (size_t)r * DHD + c8);
    }
    stage_kv(0, 0);
    CP_COMMIT();

    // ldmatrix lane addressing
    const int aRow = wid * 16 + ((lane >> 3) & 1) * 8 + (lane & 7);
    const int aK   = (lane >> 4) * 8;
    const int bRow = (lane >> 4) * 8 + (lane & 7);          // K: + nbp*16
    const int bK   = ((lane >> 3) & 1) * 8;
    const int vRow = ((lane >> 3) & 1) * 8 + (lane & 7);    // V: + ks*16
    const int vCol = (lane >> 4) * 8;                       // V: + nbp*16
    const int gid  = lane >> 2;
    const int tig  = lane & 3;

    float oacc[8][4];
    float m_i[2], l_i[2];
#pragma unroll
    for (int nb = 0; nb < 8; nb++)
#pragma unroll
        for (int q = 0; q < 4; q++) oacc[nb][q] = 0.0f;
    m_i[0] = m_i[1] = -1e30f;
    l_i[0] = l_i[1] = 0.0f;

    const int NT = SEQ / 64;   // 32
    for (int c = 0; c < NT; c++) {
        if (c + 1 < NT) {
            stage_kv((c + 1) & 1, (c + 1) * 64);
            CP_COMMIT();
            CP_WAIT1();
        } else {
            CP_WAIT0();
        }
        __syncthreads();

        const uint32_t kvb = sb + KVBASE + (c & 1) * KVSTAGE;
        const uint32_t uKH = kvb, uKL = kvb + KARR;
        const uint32_t uVH = kvb + 2 * KARR, uVL = kvb + 3 * KARR;

        // ---- S = Q @ K^T ----
        float sacc[8][4];
#pragma unroll
        for (int nb = 0; nb < 8; nb++)
#pragma unroll
            for (int q = 0; q < 4; q++) sacc[nb][q] = 0.0f;

#pragma unroll
        for (int ks = 0; ks < 4; ks++) {
            uint32_t ah[4], al[4];
            uint32_t qoff = (uint32_t)(aRow * QST + ks * 16 + aK) * 2;
            ldm4(ah, uQH + qoff);
            ldm4(al, uQL + qoff);
#pragma unroll
            for (int nbp = 0; nbp < 4; nbp++) {
                uint32_t koff = (uint32_t)((bRow + nbp * 16) * QST +
                                           ks * 16 + bK) * 2;
                uint32_t th[4], tl[4];
                ldm4(th, uKH + koff);
                ldm4(tl, uKL + koff);
                mma16816(sacc[2 * nbp],     ah, th);
                mma16816(sacc[2 * nbp + 1], ah, th + 2);
                mma16816(sacc[2 * nbp],     ah, tl);
                mma16816(sacc[2 * nbp + 1], ah, tl + 2);
                mma16816(sacc[2 * nbp],     al, th);
                mma16816(sacc[2 * nbp + 1], al, th + 2);
            }
        }

        // ---- Online softmax (register-resident) ----
#pragma unroll
        for (int hr = 0; hr < 2; hr++) {
            float mloc = -1e30f;
#pragma unroll
            for (int nb = 0; nb < 8; nb++)
                mloc = fmaxf(mloc, fmaxf(sacc[nb][2 * hr], sacc[nb][2 * hr + 1]));
            mloc = fmaxf(mloc, __shfl_xor_sync(0xffffffffu, mloc, 1));
            mloc = fmaxf(mloc, __shfl_xor_sync(0xffffffffu, mloc, 2));
            float mnew = fmaxf(m_i[hr], mloc);
            float sc   = __expf(m_i[hr] - mnew);
            m_i[hr] = mnew;
            float ssum = 0.0f;
#pragma unroll
            for (int nb = 0; nb < 8; nb++) {
                float p0 = __expf(sacc[nb][2 * hr]     - mnew);
                float p1 = __expf(sacc[nb][2 * hr + 1] - mnew);
                sacc[nb][2 * hr]     = p0;
                sacc[nb][2 * hr + 1] = p1;
                ssum += p0 + p1;
            }
            ssum += __shfl_xor_sync(0xffffffffu, ssum, 1);
            ssum += __shfl_xor_sync(0xffffffffu, ssum, 2);
            l_i[hr] = l_i[hr] * sc + ssum;
#pragma unroll
            for (int nb = 0; nb < 8; nb++) {
                oacc[nb][2 * hr]     *= sc;
                oacc[nb][2 * hr + 1] *= sc;
            }
        }

        // ---- Pack P -> bf16 hi/lo A-fragments (registers only) ----
        uint32_t ph[4][4], pl[4][4];
#pragma unroll
        for (int ks = 0; ks < 4; ks++) {
            split2(sacc[2 * ks][0],     sacc[2 * ks][1],     ph[ks][0], pl[ks][0]);
            split2(sacc[2 * ks][2],     sacc[2 * ks][3],     ph[ks][1], pl[ks][1]);
            split2(sacc[2 * ks + 1][0], sacc[2 * ks + 1][1], ph[ks][2], pl[ks][2]);
            split2(sacc[2 * ks + 1][2], sacc[2 * ks + 1][3], ph[ks][3], pl[ks][3]);
        }

        // ---- O += P @ V (V fragments via ldmatrix.trans) ----
#pragma unroll
        for (int ks = 0; ks < 4; ks++) {
#pragma unroll
            for (int nbp = 0; nbp < 4; nbp++) {
                uint32_t voff = (uint32_t)((ks * 16 + vRow) * QST +
                                           nbp * 16 + vCol) * 2;
                uint32_t th[4], tl[4];
                ldm4t(th, uVH + voff);
                ldm4t(tl, uVL + voff);
                mma16816(oacc[2 * nbp],     ph[ks], th);
                mma16816(oacc[2 * nbp + 1], ph[ks], th + 2);
                mma16816(oacc[2 * nbp],     ph[ks], tl);
                mma16816(oacc[2 * nbp + 1], ph[ks], tl + 2);
                mma16816(oacc[2 * nbp],     pl[ks], th);
                mma16816(oacc[2 * nbp + 1], pl[ks], th + 2);
            }
        }
        __syncthreads();
    }

    // ---- Write normalized, pre-split output in [B,S,D] layout ----
    const int b = bh >> 4;
    const int h = bh & 15;
#pragma unroll
    for (int hr = 0; hr < 2; hr++) {
        int q = q0 + wid * 16 + gid + hr * 8;
        float inv = 1.0f / l_i[hr];
        size_t base = (size_t)(b * SEQ + q) * DM + h * DHD;
#pragma unroll
        for (int nb = 0; nb < 8; nb++) {
            float ox = oacc[nb][2 * hr]     * inv;
            float oy = oacc[nb][2 * hr + 1] * inv;
            uint32_t hp, lp;
            split2(ox, oy, hp, lp);
            size_t idx = base + nb * 8 + 2 * tig;
            *reinterpret_cast<uint32_t*>(&AOh[idx]) = hp;
            *reinterpret_cast<uint32_t*>(&AOl[idx]) = lp;
        }
    }
}

// ---------------------------------------------------------------------------
// Launch
// ---------------------------------------------------------------------------
extern "C" void kernel_launch(void* const* d_in, const int* in_sizes, int n_in,
                              void* d_out, int out_size)
{
    const float* x  = (const float*)d_in[0];
    const float* Wq = (const float*)d_in[1];
    const float* bq = (const float*)d_in[2];
    const float* Wk = (const float*)d_in[3];
    const float* bk = (const float*)d_in[4];
    const float* Wv = (const float*)d_in[5];
    const float* bv = (const float*)d_in[6];
    const float* Wo = (const float*)d_in[7];
    const float* bo = (const float*)d_in[8];

    __nv_bfloat16 *xh, *xl, *Wth, *Wtl;
    __nv_bfloat16 *Qh, *Ql, *Kh, *Kl, *Vh, *Vl, *AOh, *AOl;
    cudaGetSymbolAddress((void**)&xh,  g_xh);
    cudaGetSymbolAddress((void**)&xl,  g_xl);
    cudaGetSymbolAddress((void**)&Wth, g_Wth);
    cudaGetSymbolAddress((void**)&Wtl, g_Wtl);
    cudaGetSymbolAddress((void**)&Qh,  g_Qh);
    cudaGetSymbolAddress((void**)&Ql,  g_Ql);
    cudaGetSymbolAddress((void**)&Kh,  g_Kh);
    cudaGetSymbolAddress((void**)&Kl,  g_Kl);
    cudaGetSymbolAddress((void**)&Vh,  g_Vh);
    cudaGetSymbolAddress((void**)&Vl,  g_Vl);
    cudaGetSymbolAddress((void**)&AOh, g_AOh);
    cudaGetSymbolAddress((void**)&AOl, g_AOl);

    cudaFuncSetAttribute(gemm_bf16,
                         cudaFuncAttributeMaxDynamicSharedMemorySize, GEMM_SMEM);
    cudaFuncSetAttribute(attn_mma,
                         cudaFuncAttributeMaxDynamicSharedMemorySize, ATTN_SMEM);

    const size_t WSZ = 1024 * 1024;

    // Pre-split inputs
    split_x<<<4096, 256>>>(x, xh, xl);
    split_wt<<<1024, 256>>>(Wq, Wth + 0 * WSZ, Wtl + 0 * WSZ);
    split_wt<<<1024, 256>>>(Wk, Wth + 1 * WSZ, Wtl + 1 * WSZ);
    split_wt<<<1024, 256>>>(Wv, Wth + 2 * WSZ, Wtl + 2 * WSZ);
    split_wt<<<1024, 256>>>(Wo, Wth + 3 * WSZ, Wtl + 3 * WSZ);

    dim3 gGemm(GN / 128, GM / 128);   // (8, 32)

    gemm_bf16<<<gGemm, 256, GEMM_SMEM>>>(xh, xl, Wth + 0 * WSZ, Wtl + 0 * WSZ,
                                         bq, nullptr, Qh, Ql, 0.125f, 1);
    gemm_bf16<<<gGemm, 256, GEMM_SMEM>>>(xh, xl, Wth + 1 * WSZ, Wtl + 1 * WSZ,
                                         bk, nullptr, Kh, Kl, 1.0f, 1);
    gemm_bf16<<<gGemm, 256, GEMM_SMEM>>>(xh, xl, Wth + 2 * WSZ, Wtl + 2 * WSZ,
                                         bv, nullptr, Vh, Vl, 1.0f, 1);

    attn_mma<<<dim3(SEQ / 128, BB * HH), 256, ATTN_SMEM>>>(
        Qh, Ql, Kh, Kl, Vh, Vl, AOh, AOl);

    gemm_bf16<<<gGemm, 256, GEMM_SMEM>>>(AOh, AOl, Wth + 3 * WSZ, Wtl + 3 * WSZ,
                                         bo, (float*)d_out, nullptr, nullptr,
                                         1.0f, 0);
}

// round 10
// speedup vs baseline: 2.6523x; 1.0095x over previous
#include <cuda_runtime.h>
#include <cuda_bf16.h>
#include <math.h>
#include <stdint.h>

// Problem constants
#define BB   2
#define SEQ  2048
#define DM   1024
#define HH   16
#define DHD  64

// Pre-split inputs / intermediates (bf16 hi + lo residual)
__device__ __nv_bfloat16 g_xh [4096*1024];
__device__ __nv_bfloat16 g_xl [4096*1024];
__device__ __nv_bfloat16 g_Wth[4][1024*1024];   // W^T [n][k]
__device__ __nv_bfloat16 g_Wtl[4][1024*1024];
__device__ __nv_bfloat16 g_Qh[BB*HH*SEQ*DHD];
__device__ __nv_bfloat16 g_Ql[BB*HH*SEQ*DHD];
__device__ __nv_bfloat16 g_Kh[BB*HH*SEQ*DHD];
__device__ __nv_bfloat16 g_Kl[BB*HH*SEQ*DHD];
__device__ __nv_bfloat16 g_Vh[BB*HH*SEQ*DHD];
__device__ __nv_bfloat16 g_Vl[BB*HH*SEQ*DHD];
__device__ __nv_bfloat16 g_AOh[BB*SEQ*DM];
__device__ __nv_bfloat16 g_AOl[BB*SEQ*DM];

// ---------------------------------------------------------------------------
// helpers
// ---------------------------------------------------------------------------
__device__ __forceinline__ uint32_t smem_u32(const void* p) {
    uint32_t a;
    asm("{ .reg .u64 t; cvta.to.shared.u64 t, %1; cvt.u32.u64 %0, t; }"
        : "=r"(a) : "l"(p));
    return a;
}
__device__ __forceinline__ void ldm4(uint32_t* r, uint32_t addr) {
    asm volatile("ldmatrix.sync.aligned.m8n8.x4.shared.b16 {%0,%1,%2,%3}, [%4];"
        : "=r"(r[0]), "=r"(r[1]), "=r"(r[2]), "=r"(r[3]) : "r"(addr));
}
__device__ __forceinline__ void ldm4t(uint32_t* r, uint32_t addr) {
    asm volatile("ldmatrix.sync.aligned.m8n8.x4.trans.shared.b16 {%0,%1,%2,%3}, [%4];"
        : "=r"(r[0]), "=r"(r[1]), "=r"(r[2]), "=r"(r[3]) : "r"(addr));
}
__device__ __forceinline__ void mma16816(float* c, const uint32_t* a,
                                         const uint32_t* b) {
    asm volatile(
        "mma.sync.aligned.m16n8k16.row.col.f32.bf16.bf16.f32 "
        "{%0,%1,%2,%3}, {%4,%5,%6,%7}, {%8,%9}, {%0,%1,%2,%3};"
        : "+f"(c[0]), "+f"(c[1]), "+f"(c[2]), "+f"(c[3])
        : "r"(a[0]), "r"(a[1]), "r"(a[2]), "r"(a[3]), "r"(b[0]), "r"(b[1]));
}
__device__ __forceinline__ void split2(float x, float y,
                                       uint32_t& h, uint32_t& l) {
    __nv_bfloat162 hh = __floats2bfloat162_rn(x, y);
    __nv_bfloat162 ll = __floats2bfloat162_rn(x - __bfloat162float(hh.x),
                                              y - __bfloat162float(hh.y));
    h = *reinterpret_cast<uint32_t*>(&hh);
    l = *reinterpret_cast<uint32_t*>(&ll);
}
__device__ __forceinline__ float ex2(float x) {
    float r;
    asm("ex2.approx.ftz.f32 %0, %1;" : "=f"(r) : "f"(x));
    return r;
}

#define CPA16(dst, src) \
    asm volatile("cp.async.cg.shared.global [%0], [%1], 16;" \
                 :: "r"(dst), "l"(src))
#define CP_COMMIT() asm volatile("cp.async.commit_group;" ::: "memory")
#define CP_WAIT2()  asm volatile("cp.async.wait_group 2;" ::: "memory")
#define CP_WAIT1()  asm volatile("cp.async.wait_group 1;" ::: "memory")
#define CP_WAIT0()  asm volatile("cp.async.wait_group 0;" ::: "memory")

// 0.125 * log2(e): folded into Q so attention can use ex2 directly
#define QSCALE 0.18033688011112042f

// ---------------------------------------------------------------------------
// Precompute: split x into bf16 hi/lo
// ---------------------------------------------------------------------------
__global__ __launch_bounds__(256)
void split_x(const float* __restrict__ src,
             __nv_bfloat16* __restrict__ h,
             __nv_bfloat16* __restrict__ l)
{
    int i = blockIdx.x * 256 + threadIdx.x;
    float4 v = reinterpret_cast<const float4*>(src)[i];
    uint32_t h0, l0, h1, l1;
    split2(v.x, v.y, h0, l0);
    split2(v.z, v.w, h1, l1);
    uint2 hp; hp.x = h0; hp.y = h1;
    uint2 lp; lp.x = l0; lp.y = l1;
    reinterpret_cast<uint2*>(h)[i] = hp;
    reinterpret_cast<uint2*>(l)[i] = lp;
}

// ---------------------------------------------------------------------------
// Precompute: transpose W [k][n] -> [n][k], split hi/lo
// ---------------------------------------------------------------------------
__global__ __launch_bounds__(256)
void split_wt(const float* __restrict__ W,
              __nv_bfloat16* __restrict__ Th,
              __nv_bfloat16* __restrict__ Tl)
{
    __shared__ float t[32][33];
    const int tid = threadIdx.x;
    const int n0 = (blockIdx.x & 31) * 32;
    const int k0 = (blockIdx.x >> 5) * 32;
#pragma unroll
    for (int it = 0; it < 4; it++) {
        int id = tid + it * 256;
        int r = id >> 5, c = id & 31;
        t[r][c] = W[(size_t)(k0 + r) * 1024 + n0 + c];
    }
    __syncthreads();
    const int rn = tid >> 3;
    const int c4 = tid & 7;
    uint32_t h0, l0, h1, l1;
    split2(t[c4 * 4 + 0][rn], t[c4 * 4 + 1][rn], h0, l0);
    split2(t[c4 * 4 + 2][rn], t[c4 * 4 + 3][rn], h1, l1);
    size_t o = ((size_t)(n0 + rn) * 1024 + k0 + c4 * 4) >> 1;
    uint2 hp; hp.x = h0; hp.y = h1;
    uint2 lp; lp.x = l0; lp.y = l1;
    *reinterpret_cast<uint2*>(reinterpret_cast<uint32_t*>(Th) + o) = hp;
    *reinterpret_cast<uint2*>(reinterpret_cast<uint32_t*>(Tl) + o) = lp;
}

// ---------------------------------------------------------------------------
// bf16x3 GEMM core, cp.async double-buffered. CTA 128x128, BK=32, 8 warps.
// ---------------------------------------------------------------------------
constexpr int GM = 4096, GN = 1024, GK = 1024;
constexpr int BK = 32;
constexpr int AST = 40;
constexpr int ARR_B   = 128 * AST * 2;
constexpr int STAGE_B = 4 * ARR_B;
constexpr int GEMM_SMEM = 2 * STAGE_B;          // 81920 B

__device__ __forceinline__
void gemm_core(const __nv_bfloat16* __restrict__ Ah,
               const __nv_bfloat16* __restrict__ Al,
               const __nv_bfloat16* __restrict__ Bth,
               const __nv_bfloat16* __restrict__ Btl,
               const float* __restrict__ bias,
               float* __restrict__ C,
               __nv_bfloat16* __restrict__ Ch,
               __nv_bfloat16* __restrict__ Cl,
               float scale, int splitHeads,
               int mBase, int nBase, char* smem)
{
    const uint32_t sb = smem_u32(smem);
    const int tid  = threadIdx.x;
    const int wid  = tid >> 5;
    const int lane = tid & 31;
    const int wm   = wid & 1;
    const int wn   = wid >> 1;

    const int sr0 = tid >> 2,         sc0 = (tid & 3) * 8;
    const int sr1 = (tid + 256) >> 2, sc1 = ((tid + 256) & 3) * 8;

    auto stage = [&](int st, int k0) {
        uint32_t d = sb + st * STAGE_B;
        uint32_t o0 = (uint32_t)(sr0 * AST + sc0) * 2;
        uint32_t o1 = (uint32_t)(sr1 * AST + sc1) * 2;
        CPA16(d + 0 * ARR_B + o0, Ah  + (size_t)(mBase + sr0) * GK + k0 + sc0);
        CPA16(d + 0 * ARR_B + o1, Ah  + (size_t)(mBase + sr1) * GK + k0 + sc1);
        CPA16(d + 1 * ARR_B + o0, Al  + (size_t)(mBase + sr0) * GK + k0 + sc0);
        CPA16(d + 1 * ARR_B + o1, Al  + (size_t)(mBase + sr1) * GK + k0 + sc1);
        CPA16(d + 2 * ARR_B + o0, Bth + (size_t)(nBase + sr0) * GK + k0 + sc0);
        CPA16(d + 2 * ARR_B + o1, Bth + (size_t)(nBase + sr1) * GK + k0 + sc1);
        CPA16(d + 3 * ARR_B + o0, Btl + (size_t)(nBase + sr0) * GK + k0 + sc0);
        CPA16(d + 3 * ARR_B + o1, Btl + (size_t)(nBase + sr1) * GK + k0 + sc1);
    };

    float acc[4][4][4];
#pragma unroll
    for (int i = 0; i < 4; i++)
#pragma unroll
        for (int j = 0; j < 4; j++)
#pragma unroll
            for (int q = 0; q < 4; q++) acc[i][j][q] = 0.0f;

    const int aRow = wm * 64 + ((lane >> 3) & 1) * 8 + (lane & 7);
    const int aKel = (lane >> 4) * 8;
    const int bRow = wn * 32 + (lane >> 4) * 8 + (lane & 7);
    const int bKel = ((lane >> 3) & 1) * 8;

    stage(0, 0);
    CP_COMMIT();

    const int NCHUNK = GK / BK;   // 32
    for (int c = 0; c < NCHUNK; c++) {
        if (c + 1 < NCHUNK) {
            stage((c + 1) & 1, (c + 1) * BK);
            CP_COMMIT();
            CP_WAIT1();
        } else {
            CP_WAIT0();
        }
        __syncthreads();

        const uint32_t base = sb + (c & 1) * STAGE_B;
        const uint32_t uAh = base, uAl = base + ARR_B;
        const uint32_t uBh = base + 2 * ARR_B, uBl = base + 3 * ARR_B;

#pragma unroll
        for (int ks = 0; ks < 2; ks++) {
            uint32_t ah[4][4], al[4][4];
#pragma unroll
            for (int mb = 0; mb < 4; mb++) {
                uint32_t off = (uint32_t)((aRow + mb * 16) * AST +
                                          ks * 16 + aKel) * 2;
                ldm4(ah[mb], uAh + off);
                ldm4(al[mb], uAl + off);
            }
            uint32_t bh[4][2], bl[4][2];
#pragma unroll
            for (int nbp = 0; nbp < 2; nbp++) {
                uint32_t off = (uint32_t)((bRow + nbp * 16) * AST +
                                          ks * 16 + bKel) * 2;
                uint32_t th[4], tl[4];
                ldm4(th, uBh + off);
                ldm4(tl, uBl + off);
                bh[nbp * 2][0] = th[0]; bh[nbp * 2][1] = th[1];
                bh[nbp * 2 + 1][0] = th[2]; bh[nbp * 2 + 1][1] = th[3];
                bl[nbp * 2][0] = tl[0]; bl[nbp * 2][1] = tl[1];
                bl[nbp * 2 + 1][0] = tl[2]; bl[nbp * 2 + 1][1] = tl[3];
            }
#pragma unroll
            for (int mb = 0; mb < 4; mb++)
#pragma unroll
                for (int nb = 0; nb < 4; nb++) {
                    mma16816(acc[mb][nb], ah[mb], bh[nb]);
                    mma16816(acc[mb][nb], ah[mb], bl[nb]);
                    mma16816(acc[mb][nb], al[mb], bh[nb]);
                }
        }
        __syncthreads();
    }

    const int gid = lane >> 2;
    const int tig = lane & 3;
#pragma unroll
    for (int nb = 0; nb < 4; nb++) {
        int col = nBase + wn * 32 + nb * 8 + 2 * tig;
        float2 bv = *reinterpret_cast<const float2*>(bias + col);
#pragma unroll
        for (int mb = 0; mb < 4; mb++) {
            int row0 = mBase + wm * 64 + mb * 16 + gid;
#pragma unroll
            for (int half = 0; half < 2; half++) {
                int row = row0 + half * 8;
                float ox = (acc[mb][nb][half * 2 + 0] + bv.x) * scale;
                float oy = (acc[mb][nb][half * 2 + 1] + bv.y) * scale;
                if (splitHeads) {
                    int b = row >> 11, s = row & (SEQ - 1);
                    int h = col >> 6, dh = col & (DHD - 1);
                    size_t idx = (((size_t)(b * HH + h) * SEQ + s) * DHD) + dh;
                    uint32_t hp, lp;
                    split2(ox, oy, hp, lp);
                    *reinterpret_cast<uint32_t*>(&Ch[idx]) = hp;
                    *reinterpret_cast<uint32_t*>(&Cl[idx]) = lp;
                } else {
                    float2 o; o.x = ox; o.y = oy;
                    *reinterpret_cast<float2*>(&C[(size_t)row * GN + col]) = o;
                }
            }
        }
    }
}

// Fused Q/K/V projection: grid (24, 32); blockIdx.x>>3 selects the matrix.
__global__ __launch_bounds__(256, 1)
void gemm_qkv(const __nv_bfloat16* __restrict__ xh,
              const __nv_bfloat16* __restrict__ xl,
              const __nv_bfloat16* __restrict__ Wth,
              const __nv_bfloat16* __restrict__ Wtl,
              const float* __restrict__ bq,
              const float* __restrict__ bk,
              const float* __restrict__ bv,
              __nv_bfloat16* Qh, __nv_bfloat16* Ql,
              __nv_bfloat16* Kh, __nv_bfloat16* Kl,
              __nv_bfloat16* Vh, __nv_bfloat16* Vl)
{
    extern __shared__ __align__(16) char smem[];
    const int mat = blockIdx.x >> 3;
    const int nBase = (blockIdx.x & 7) * 128;
    const int mBase = blockIdx.y * 128;
    const float* bias = (mat == 0) ? bq : ((mat == 1) ? bk : bv);
    __nv_bfloat16* Ch = (mat == 0) ? Qh : ((mat == 1) ? Kh : Vh);
    __nv_bfloat16* Cl = (mat == 0) ? Ql : ((mat == 1) ? Kl : Vl);
    float scale = (mat == 0) ? QSCALE : 1.0f;
    gemm_core(xh, xl, Wth + (size_t)mat * 1048576, Wtl + (size_t)mat * 1048576,
              bias, nullptr, Ch, Cl, scale, 1, mBase, nBase, smem);
}

// Output projection
__global__ __launch_bounds__(256, 1)
void gemm_o(const __nv_bfloat16* __restrict__ AOh,
            const __nv_bfloat16* __restrict__ AOl,
            const __nv_bfloat16* __restrict__ Wth,
            const __nv_bfloat16* __restrict__ Wtl,
            const float* __restrict__ bo,
            float* __restrict__ C)
{
    extern __shared__ __align__(16) char smem[];
    gemm_core(AOh, AOl, Wth, Wtl, bo, C, nullptr, nullptr, 1.0f, 0,
              blockIdx.y * 128, blockIdx.x * 128, smem);
}

// ---------------------------------------------------------------------------
// Tensor-core flash attention with deferred-PV pipeline.
// CTA = 128 queries of one (b,h); 8 warps; 64-key tiles; 4-stage cp.async
// KV ring. Softmax of tile c overlaps PV mma of tile c-1.
// Logits are in log2 domain (Q pre-scaled by 0.125*log2 e) -> ex2.
// ---------------------------------------------------------------------------
constexpr int QST = 72;
constexpr int AQH = 0;                        // [128][QST]
constexpr int AQL = AQH + 128 * QST * 2;
constexpr int KVBASE = AQL + 128 * QST * 2;   // 36864
constexpr int KARR = 64 * QST * 2;            // 9216
constexpr int KVSTAGE = 4 * KARR;             // 36864
constexpr int NSTAGE = 4;
constexpr int ATTN_SMEM = KVBASE + NSTAGE * KVSTAGE;   // 184320

__global__ __launch_bounds__(256, 1)
void attn_mma(const __nv_bfloat16* __restrict__ Qh,
              const __nv_bfloat16* __restrict__ Ql,
              const __nv_bfloat16* __restrict__ Kh,
              const __nv_bfloat16* __restrict__ Kl,
              const __nv_bfloat16* __restrict__ Vh,
              const __nv_bfloat16* __restrict__ Vl,
              __nv_bfloat16* __restrict__ AOh,
              __nv_bfloat16* __restrict__ AOl)
{
    extern __shared__ __align__(16) char smem[];
    const uint32_t sb = smem_u32(smem);
    const uint32_t uQH = sb + AQH, uQL = sb + AQL;

    const int tid  = threadIdx.x;
    const int wid  = tid >> 5;
    const int lane = tid & 31;
    const int bh   = blockIdx.y;
    const int q0   = blockIdx.x * 128;

    const size_t baseQ = ((size_t)bh * SEQ + q0) * DHD;
    const size_t baseK = (size_t)bh * SEQ * DHD;

    const int kr0 = tid >> 3,         kc0 = (tid & 7) * 8;
    const int kr1 = (tid + 256) >> 3, kc1 = ((tid + 256) & 7) * 8;

    auto stage_kv = [&](int st, int kt) {
        uint32_t d = sb + KVBASE + st * KVSTAGE;
        size_t s0 = baseK + (size_t)(kt + kr0) * DHD + kc0;
        size_t s1 = baseK + (size_t)(kt + kr1) * DHD + kc1;
        uint32_t o0 = (uint32_t)(kr0 * QST + kc0) * 2;
        uint32_t o1 = (uint32_t)(kr1 * QST + kc1) * 2;
        CPA16(d + 0 * KARR + o0, Kh + s0);
        CPA16(d + 0 * KARR + o1, Kh + s1);
        CPA16(d + 1 * KARR + o0, Kl + s0);
        CPA16(d + 1 * KARR + o1, Kl + s1);
        CPA16(d + 2 * KARR + o0, Vh + s0);
        CPA16(d + 2 * KARR + o1, Vh + s1);
        CPA16(d + 3 * KARR + o0, Vl + s0);
        CPA16(d + 3 * KARR + o1, Vl + s1);
    };

    // Prologue: stage Q + tiles 0, 1
#pragma unroll
    for (int it = 0; it < 4; it++) {
        int id = tid + it * 256;
        int r = id >> 3, c8 = (id & 7) * 8;
        uint32_t o = (uint32_t)(r * QST + c8) * 2;
        CPA16(uQH + o, Qh + baseQ + (size_t)r * DHD + c8);
        CPA16(uQL + o, Ql + baseQ + (size_t)r * DHD + c8);
    }
    stage_kv(0, 0);
    CP_COMMIT();
    stage_kv(1, 64);
    CP_COMMIT();

    // ldmatrix lane addressing
    const int aRow = wid * 16 + ((lane >> 3) & 1) * 8 + (lane & 7);
    const int aK   = (lane >> 4) * 8;
    const int bRow = (lane >> 4) * 8 + (lane & 7);
    const int bK   = ((lane >> 3) & 1) * 8;
    const int vRow = ((lane >> 3) & 1) * 8 + (lane & 7);
    const int vCol = (lane >> 4) * 8;
    const int gid  = lane >> 2;
    const int tig  = lane & 3;

    float oacc[8][4];
    float m_i[2], l_p[2];
    uint32_t ph[4][4], pl[4][4];
#pragma unroll
    for (int nb = 0; nb < 8; nb++)
#pragma unroll
        for (int q = 0; q < 4; q++) oacc[nb][q] = 0.0f;
    m_i[0] = m_i[1] = -1e30f;
    l_p[0] = l_p[1] = 0.0f;

    // PV for one stage buffer using current ph/pl
    auto pv = [&](int st) {
        uint32_t kvb = sb + KVBASE + st * KVSTAGE;
        uint32_t uVH = kvb + 2 * KARR, uVL = kvb + 3 * KARR;
#pragma unroll
        for (int ks = 0; ks < 4; ks++) {
#pragma unroll
            for (int nbp = 0; nbp < 4; nbp++) {
                uint32_t voff = (uint32_t)((ks * 16 + vRow) * QST +
                                           nbp * 16 + vCol) * 2;
                uint32_t th[4], tl[4];
                ldm4t(th, uVH + voff);
                ldm4t(tl, uVL + voff);
                mma16816(oacc[2 * nbp],     ph[ks], th);
                mma16816(oacc[2 * nbp + 1], ph[ks], th + 2);
                mma16816(oacc[2 * nbp],     ph[ks], tl);
                mma16816(oacc[2 * nbp + 1], ph[ks], tl + 2);
                mma16816(oacc[2 * nbp],     pl[ks], th);
                mma16816(oacc[2 * nbp + 1], pl[ks], th + 2);
            }
        }
    };

    const int NT = SEQ / 64;   // 32
    for (int c = 0; c < NT; c++) {
        // protect ring buffer (c+2)%4 (tile c-2 readers finished iter c-1)
        __syncthreads();
        if (c + 2 < NT) stage_kv((c + 2) & 3, (c + 2) * 64);
        CP_COMMIT();
        CP_WAIT2();            // tile c arrived (groups c+1, c+2 may be pending)
        __syncthreads();

        const uint32_t kvb = sb + KVBASE + (c & 3) * KVSTAGE;
        const uint32_t uKH = kvb, uKL = kvb + KARR;

        // ---- S = Q @ K^T ----
        float sacc[8][4];
#pragma unroll
        for (int nb = 0; nb < 8; nb++)
#pragma unroll
            for (int q = 0; q < 4; q++) sacc[nb][q] = 0.0f;

#pragma unroll
        for (int ks = 0; ks < 4; ks++) {
            uint32_t ahf[4], alf[4];
            uint32_t qoff = (uint32_t)(aRow * QST + ks * 16 + aK) * 2;
            ldm4(ahf, uQH + qoff);
            ldm4(alf, uQL + qoff);
#pragma unroll
            for (int nbp = 0; nbp < 4; nbp++) {
                uint32_t koff = (uint32_t)((bRow + nbp * 16) * QST +
                                           ks * 16 + bK) * 2;
                uint32_t th[4], tl[4];
                ldm4(th, uKH + koff);
                ldm4(tl, uKL + koff);
                mma16816(sacc[2 * nbp],     ahf, th);
                mma16816(sacc[2 * nbp + 1], ahf, th + 2);
                mma16816(sacc[2 * nbp],     ahf, tl);
                mma16816(sacc[2 * nbp + 1], ahf, tl + 2);
                mma16816(sacc[2 * nbp],     alf, th);
                mma16816(sacc[2 * nbp + 1], alf, th + 2);
            }
        }

        // ---- Deferred PV of previous tile (overlaps softmax below) ----
        if (c > 0) pv((c - 1) & 3);

        // ---- Softmax stats (log2 domain, no oacc dependence yet) ----
        float sc0, sc1;
        {
#pragma unroll
            for (int hr = 0; hr < 2; hr++) {
                float mloc = -1e30f;
#pragma unroll
                for (int nb = 0; nb < 8; nb++)
                    mloc = fmaxf(mloc,
                                 fmaxf(sacc[nb][2 * hr], sacc[nb][2 * hr + 1]));
                mloc = fmaxf(mloc, __shfl_xor_sync(0xffffffffu, mloc, 1));
                mloc = fmaxf(mloc, __shfl_xor_sync(0xffffffffu, mloc, 2));
                float mnew = fmaxf(m_i[hr], mloc);
                float sc = ex2(m_i[hr] - mnew);
                m_i[hr] = mnew;
                float psum = 0.0f;
#pragma unroll
                for (int nb = 0; nb < 8; nb++) {
                    float p0 = ex2(sacc[nb][2 * hr]     - mnew);
                    float p1 = ex2(sacc[nb][2 * hr + 1] - mnew);
                    sacc[nb][2 * hr]     = p0;
                    sacc[nb][2 * hr + 1] = p1;
                    psum += p0 + p1;
                }
                l_p[hr] = l_p[hr] * sc + psum;   // per-thread partial
                if (hr == 0) sc0 = sc; else sc1 = sc;
            }
        }

        // ---- Rescale O (after PV(c-1) has accumulated) ----
#pragma unroll
        for (int nb = 0; nb < 8; nb++) {
            oacc[nb][0] *= sc0; oacc[nb][1] *= sc0;
            oacc[nb][2] *= sc1; oacc[nb][3] *= sc1;
        }

        // ---- Pack P -> bf16 hi/lo fragments for next iteration's PV ----
#pragma unroll
        for (int ks = 0; ks < 4; ks++) {
            split2(sacc[2 * ks][0],     sacc[2 * ks][1],     ph[ks][0], pl[ks][0]);
            split2(sacc[2 * ks][2],     sacc[2 * ks][3],     ph[ks][1], pl[ks][1]);
            split2(sacc[2 * ks + 1][0], sacc[2 * ks + 1][1], ph[ks][2], pl[ks][2]);
            split2(sacc[2 * ks + 1][2], sacc[2 * ks + 1][3], ph[ks][3], pl[ks][3]);
        }
    }

    // Final pending PV
    pv((NT - 1) & 3);

    // ---- Final l reduction (deferred across tiles) ----
    float l0 = l_p[0];
    l0 += __shfl_xor_sync(0xffffffffu, l0, 1);
    l0 += __shfl_xor_sync(0xffffffffu, l0, 2);
    float l1 = l_p[1];
    l1 += __shfl_xor_sync(0xffffffffu, l1, 1);
    l1 += __shfl_xor_sync(0xffffffffu, l1, 2);

    // ---- Write normalized, pre-split output in [B,S,D] layout ----
    const int b = bh >> 4;
    const int h = bh & 15;
#pragma unroll
    for (int hr = 0; hr < 2; hr++) {
        int q = q0 + wid * 16 + gid + hr * 8;
        float inv = 1.0f / (hr ? l1 : l0);
        size_t base = (size_t)(b * SEQ + q) * DM + h * DHD;
#pragma unroll
        for (int nb = 0; nb < 8; nb++) {
            float ox = oacc[nb][2 * hr]     * inv;
            float oy = oacc[nb][2 * hr + 1] * inv;
            uint32_t hp, lp;
            split2(ox, oy, hp, lp);
            size_t idx = base + nb * 8 + 2 * tig;
            *reinterpret_cast<uint32_t*>(&AOh[idx]) = hp;
            *reinterpret_cast<uint32_t*>(&AOl[idx]) = lp;
        }
    }
}

// ---------------------------------------------------------------------------
// Launch
// ---------------------------------------------------------------------------
extern "C" void kernel_launch(void* const* d_in, const int* in_sizes, int n_in,
                              void* d_out, int out_size)
{
    const float* x  = (const float*)d_in[0];
    const float* Wq = (const float*)d_in[1];
    const float* bq = (const float*)d_in[2];
    const float* Wk = (const float*)d_in[3];
    const float* bk = (const float*)d_in[4];
    const float* Wv = (const float*)d_in[5];
    const float* bv = (const float*)d_in[6];
    const float* Wo = (const float*)d_in[7];
    const float* bo = (const float*)d_in[8];

    __nv_bfloat16 *xh, *xl, *Wth, *Wtl;
    __nv_bfloat16 *Qh, *Ql, *Kh, *Kl, *Vh, *Vl, *AOh, *AOl;
    cudaGetSymbolAddress((void**)&xh,  g_xh);
    cudaGetSymbolAddress((void**)&xl,  g_xl);
    cudaGetSymbolAddress((void**)&Wth, g_Wth);
    cudaGetSymbolAddress((void**)&Wtl, g_Wtl);
    cudaGetSymbolAddress((void**)&Qh,  g_Qh);
    cudaGetSymbolAddress((void**)&Ql,  g_Ql);
    cudaGetSymbolAddress((void**)&Kh,  g_Kh);
    cudaGetSymbolAddress((void**)&Kl,  g_Kl);
    cudaGetSymbolAddress((void**)&Vh,  g_Vh);
    cudaGetSymbolAddress((void**)&Vl,  g_Vl);
    cudaGetSymbolAddress((void**)&AOh, g_AOh);
    cudaGetSymbolAddress((void**)&AOl, g_AOl);

    cudaFuncSetAttribute(gemm_qkv,
                         cudaFuncAttributeMaxDynamicSharedMemorySize, GEMM_SMEM);
    cudaFuncSetAttribute(gemm_o,
                         cudaFuncAttributeMaxDynamicSharedMemorySize, GEMM_SMEM);
    cudaFuncSetAttribute(attn_mma,
                         cudaFuncAttributeMaxDynamicSharedMemorySize, ATTN_SMEM);

    const size_t WSZ = 1024 * 1024;

    split_x<<<4096, 256>>>(x, xh, xl);
    split_wt<<<1024, 256>>>(Wq, Wth + 0 * WSZ, Wtl + 0 * WSZ);
    split_wt<<<1024, 256>>>(Wk, Wth + 1 * WSZ, Wtl + 1 * WSZ);
    split_wt<<<1024, 256>>>(Wv, Wth + 2 * WSZ, Wtl + 2 * WSZ);
    split_wt<<<1024, 256>>>(Wo, Wth + 3 * WSZ, Wtl + 3 * WSZ);

    gemm_qkv<<<dim3(24, 32), 256, GEMM_SMEM>>>(xh, xl, Wth, Wtl,
                                               bq, bk, bv,
                                               Qh, Ql, Kh, Kl, Vh, Vl);

    attn_mma<<<dim3(SEQ / 128, BB * HH), 256, ATTN_SMEM>>>(
        Qh, Ql, Kh, Kl, Vh, Vl, AOh, AOl);

    gemm_o<<<dim3(8, 32), 256, GEMM_SMEM>>>(AOh, AOl, Wth + 3 * WSZ,
                                            Wtl + 3 * WSZ, bo, (float*)d_out);
}

// round 11
// speedup vs baseline: 3.1076x; 1.1717x over previous
#include <cuda_runtime.h>
#include <cuda_bf16.h>
#include <math.h>
#include <stdint.h>

// Problem constants
#define BB   2
#define SEQ  2048
#define DM   1024
#define HH   16
#define DHD  64

// Precomputed operands (tf32-rounded fp32) + bf16 hi/lo for V
__device__ float g_xr [4096*1024];
__device__ float g_Wtr[4][1024*1024];           // W^T [n][k], tf32-rounded
__device__ float g_Qr [BB*HH*SEQ*DHD];          // pre-scaled, tf32-rounded
__device__ float g_Kr [BB*HH*SEQ*DHD];
__device__ __nv_bfloat16 g_Vh[BB*HH*SEQ*DHD];
__device__ __nv_bfloat16 g_Vl[BB*HH*SEQ*DHD];
__device__ float g_AO [BB*SEQ*DM];              // tf32-rounded

// ---------------------------------------------------------------------------
// helpers
// ---------------------------------------------------------------------------
__device__ __forceinline__ uint32_t smem_u32(const void* p) {
    uint32_t a;
    asm("{ .reg .u64 t; cvta.to.shared.u64 t, %1; cvt.u32.u64 %0, t; }"
        : "=r"(a) : "l"(p));
    return a;
}
__device__ __forceinline__ void ldm4(uint32_t* r, uint32_t addr) {
    asm volatile("ldmatrix.sync.aligned.m8n8.x4.shared.b16 {%0,%1,%2,%3}, [%4];"
        : "=r"(r[0]), "=r"(r[1]), "=r"(r[2]), "=r"(r[3]) : "r"(addr));
}
__device__ __forceinline__ void ldm4t(uint32_t* r, uint32_t addr) {
    asm volatile("ldmatrix.sync.aligned.m8n8.x4.trans.shared.b16 {%0,%1,%2,%3}, [%4];"
        : "=r"(r[0]), "=r"(r[1]), "=r"(r[2]), "=r"(r[3]) : "r"(addr));
}
// bf16 k16 mma
__device__ __forceinline__ void mma16816(float* c, const uint32_t* a,
                                         const uint32_t* b) {
    asm volatile(
        "mma.sync.aligned.m16n8k16.row.col.f32.bf16.bf16.f32 "
        "{%0,%1,%2,%3}, {%4,%5,%6,%7}, {%8,%9}, {%0,%1,%2,%3};"
        : "+f"(c[0]), "+f"(c[1]), "+f"(c[2]), "+f"(c[3])
        : "r"(a[0]), "r"(a[1]), "r"(a[2]), "r"(a[3]), "r"(b[0]), "r"(b[1]));
}
// tf32 k8 mma
__device__ __forceinline__ void mma1688(float* c, const uint32_t* a,
                                        uint32_t b0, uint32_t b1) {
    asm volatile(
        "mma.sync.aligned.m16n8k8.row.col.f32.tf32.tf32.f32 "
        "{%0,%1,%2,%3}, {%4,%5,%6,%7}, {%8,%9}, {%0,%1,%2,%3};"
        : "+f"(c[0]), "+f"(c[1]), "+f"(c[2]), "+f"(c[3])
        : "r"(a[0]), "r"(a[1]), "r"(a[2]), "r"(a[3]), "r"(b0), "r"(b1));
}
__device__ __forceinline__ float totf32(float x) {
    uint32_t u;
    asm("cvt.rna.tf32.f32 %0, %1;" : "=r"(u) : "f"(x));
    return __uint_as_float(u);
}
__device__ __forceinline__ void split2(float x, float y,
                                       uint32_t& h, uint32_t& l) {
    __nv_bfloat162 hh = __floats2bfloat162_rn(x, y);
    __nv_bfloat162 ll = __floats2bfloat162_rn(x - __bfloat162float(hh.x),
                                              y - __bfloat162float(hh.y));
    h = *reinterpret_cast<uint32_t*>(&hh);
    l = *reinterpret_cast<uint32_t*>(&ll);
}
__device__ __forceinline__ float ex2(float x) {
    float r;
    asm("ex2.approx.ftz.f32 %0, %1;" : "=f"(r) : "f"(x));
    return r;
}

#define CPA16(dst, src) \
    asm volatile("cp.async.cg.shared.global [%0], [%1], 16;" \
                 :: "r"(dst), "l"(src))
#define CP_COMMIT() asm volatile("cp.async.commit_group;" ::: "memory")
#define CP_WAIT2()  asm volatile("cp.async.wait_group 2;" ::: "memory")
#define CP_WAIT1()  asm volatile("cp.async.wait_group 1;" ::: "memory")
#define CP_WAIT0()  asm volatile("cp.async.wait_group 0;" ::: "memory")

// 0.125 * log2(e): folded into Q so attention uses ex2 directly
#define QSCALE 0.18033688011112042f

// ---------------------------------------------------------------------------
// Precompute: round x to tf32
// ---------------------------------------------------------------------------
__global__ __launch_bounds__(256)
void round_x(const float* __restrict__ src, float* __restrict__ dst)
{
    int i = blockIdx.x * 256 + threadIdx.x;
    float4 v = reinterpret_cast<const float4*>(src)[i];
    v.x = totf32(v.x); v.y = totf32(v.y);
    v.z = totf32(v.z); v.w = totf32(v.w);
    reinterpret_cast<float4*>(dst)[i] = v;
}

// Precompute: transpose W [k][n] -> [n][k], round to tf32. grid (1024, 4).
__global__ __launch_bounds__(256)
void trans_round_w(const float* __restrict__ W0,
                   const float* __restrict__ W1,
                   const float* __restrict__ W2,
                   const float* __restrict__ W3,
                   float* __restrict__ out)
{
    __shared__ float t[32][33];
    const float* Ws[4] = {W0, W1, W2, W3};
    const float* W = Ws[blockIdx.y];
    float* dst = out + (size_t)blockIdx.y * 1048576;
    const int tid = threadIdx.x;
    const int n0 = (blockIdx.x & 31) * 32;
    const int k0 = (blockIdx.x >> 5) * 32;
#pragma unroll
    for (int it = 0; it < 4; it++) {
        int id = tid + it * 256;
        int r = id >> 5, c = id & 31;
        t[r][c] = W[(size_t)(k0 + r) * 1024 + n0 + c];
    }
    __syncthreads();
    const int rn = tid >> 3;
    const int c4 = tid & 7;
    float4 o;
    o.x = totf32(t[c4 * 4 + 0][rn]);
    o.y = totf32(t[c4 * 4 + 1][rn]);
    o.z = totf32(t[c4 * 4 + 2][rn]);
    o.w = totf32(t[c4 * 4 + 3][rn]);
    *reinterpret_cast<float4*>(&dst[(size_t)(n0 + rn) * 1024 + k0 + c4 * 4]) = o;
}

// ---------------------------------------------------------------------------
// tf32 GEMM core, cp.async double-buffered. CTA 128x128, BK=32, 8 warps
// (warp tile 64x32). A [m][k], Bt [n][k], both tf32-rounded fp32.
// ---------------------------------------------------------------------------
constexpr int GM = 4096, GN = 1024, GK = 1024;
constexpr int BK = 32;
constexpr int FST = 36;                        // f32 row stride (144B)
constexpr int ARR_F = 128 * FST * 4;           // 18432 B
constexpr int STAGE_B = 2 * ARR_F;             // A + B
constexpr int GEMM_SMEM = 2 * STAGE_B;         // 73728 B

// out modes
#define MODE_F32   0   // fp32 [M,N] (final output)
#define MODE_TF32H 1   // tf32-rounded fp32, split-heads (Q/K)
#define MODE_BF16H 2   // bf16 hi/lo, split-heads (V)

__device__ __forceinline__
void gemm_core(const float* __restrict__ A,
               const float* __restrict__ Bt,
               const float* __restrict__ bias,
               float* __restrict__ Cf,
               __nv_bfloat16* __restrict__ Ch,
               __nv_bfloat16* __restrict__ Cl,
               float scale, int mode,
               int mBase, int nBase, char* smem)
{
    const uint32_t sb = smem_u32(smem);
    const int tid  = threadIdx.x;
    const int wid  = tid >> 5;
    const int lane = tid & 31;
    const int wm   = wid & 1;
    const int wn   = wid >> 1;

    auto stage = [&](int st, int k0) {
        uint32_t d = sb + st * STAGE_B;
#pragma unroll
        for (int it = 0; it < 4; it++) {
            int id = tid + it * 256;          // 0..1023 quads
            int r  = id >> 3;                 // 0..127
            int c  = id & 7;                  // quad within 32 f32
            uint32_t o = (uint32_t)(r * FST + c * 4) * 4;
            CPA16(d + o,          A  + (size_t)(mBase + r) * GK + k0 + c * 4);
            CPA16(d + ARR_F + o,  Bt + (size_t)(nBase + r) * GK + k0 + c * 4);
        }
    };

    float acc[4][4][4];
#pragma unroll
    for (int i = 0; i < 4; i++)
#pragma unroll
        for (int j = 0; j < 4; j++)
#pragma unroll
            for (int q = 0; q < 4; q++) acc[i][j][q] = 0.0f;

    // ldmatrix addressing (f32 tiles as 2x2 b16 m8n8 tiles)
    const int aRow = wm * 64 + ((lane >> 3) & 1) * 8 + (lane & 7);  // + mb*16
    const int aC   = (lane >> 4) * 4;                               // + ks*8
    const int bRow = wn * 32 + ((lane >> 3) & 1) * 8 + (lane & 7);  // + np*16
    const int bC   = (lane >> 4) * 4;

    stage(0, 0);
    CP_COMMIT();

    const int NCHUNK = GK / BK;   // 32
    for (int c = 0; c < NCHUNK; c++) {
        if (c + 1 < NCHUNK) {
            stage((c + 1) & 1, (c + 1) * BK);
            CP_COMMIT();
            CP_WAIT1();
        } else {
            CP_WAIT0();
        }
        __syncthreads();

        const uint32_t uA = sb + (c & 1) * STAGE_B;
        const uint32_t uB = uA + ARR_F;

#pragma unroll
        for (int ks = 0; ks < 4; ks++) {
            uint32_t af[4][4];
#pragma unroll
            for (int mb = 0; mb < 4; mb++)
                ldm4(af[mb], uA + (uint32_t)((aRow + mb * 16) * FST +
                                             ks * 8 + aC) * 4);
            uint32_t bf[2][4];
#pragma unroll
            for (int np = 0; np < 2; np++)
                ldm4(bf[np], uB + (uint32_t)((bRow + np * 16) * FST +
                                             ks * 8 + bC) * 4);
#pragma unroll
            for (int mb = 0; mb < 4; mb++) {
                mma1688(acc[mb][0], af[mb], bf[0][0], bf[0][2]);
                mma1688(acc[mb][1], af[mb], bf[0][1], bf[0][3]);
                mma1688(acc[mb][2], af[mb], bf[1][0], bf[1][2]);
                mma1688(acc[mb][3], af[mb], bf[1][1], bf[1][3]);
            }
        }
        __syncthreads();
    }

    const int gid = lane >> 2;
    const int tig = lane & 3;
#pragma unroll
    for (int nb = 0; nb < 4; nb++) {
        int col = nBase + wn * 32 + nb * 8 + 2 * tig;
        float2 bv = *reinterpret_cast<const float2*>(bias + col);
#pragma unroll
        for (int mb = 0; mb < 4; mb++) {
            int row0 = mBase + wm * 64 + mb * 16 + gid;
#pragma unroll
            for (int half = 0; half < 2; half++) {
                int row = row0 + half * 8;
                float ox = (acc[mb][nb][half * 2 + 0] + bv.x) * scale;
                float oy = (acc[mb][nb][half * 2 + 1] + bv.y) * scale;
                if (mode == MODE_F32) {
                    float2 o; o.x = ox; o.y = oy;
                    *reinterpret_cast<float2*>(&Cf[(size_t)row * GN + col]) = o;
                } else {
                    int b = row >> 11, s = row & (SEQ - 1);
                    int h = col >> 6, dh = col & (DHD - 1);
                    size_t idx = (((size_t)(b * HH + h) * SEQ + s) * DHD) + dh;
                    if (mode == MODE_TF32H) {
                        float2 o; o.x = totf32(ox); o.y = totf32(oy);
                        *reinterpret_cast<float2*>(&Cf[idx]) = o;
                    } else {
                        uint32_t hp, lp;
                        split2(ox, oy, hp, lp);
                        *reinterpret_cast<uint32_t*>(&Ch[idx]) = hp;
                        *reinterpret_cast<uint32_t*>(&Cl[idx]) = lp;
                    }
                }
            }
        }
    }
}

// Fused Q/K/V projection: grid (24, 32); blockIdx.x>>3 selects the matrix.
__global__ __launch_bounds__(256, 1)
void gemm_qkv(const float* __restrict__ xr,
              const float* __restrict__ Wtr,
              const float* __restrict__ bq,
              const float* __restrict__ bk,
              const float* __restrict__ bv,
              float* Qr, float* Kr,
              __nv_bfloat16* Vh, __nv_bfloat16* Vl)
{
    extern __shared__ __align__(16) char smem[];
    const int mat = blockIdx.x >> 3;
    const int nBase = (blockIdx.x & 7) * 128;
    const int mBase = blockIdx.y * 128;
    const float* bias = (mat == 0) ? bq : ((mat == 1) ? bk : bv);
    float* Cf = (mat == 0) ? Qr : Kr;
    float scale = (mat == 0) ? QSCALE : 1.0f;
    int mode = (mat == 2) ? MODE_BF16H : MODE_TF32H;
    gemm_core(xr, Wtr + (size_t)mat * 1048576, bias,
              Cf, Vh, Vl, scale, mode, mBase, nBase, smem);
}

// Output projection
__global__ __launch_bounds__(256, 1)
void gemm_o(const float* __restrict__ AO,
            const float* __restrict__ Wtr,
            const float* __restrict__ bo,
            float* __restrict__ C)
{
    extern __shared__ __align__(16) char smem[];
    gemm_core(AO, Wtr, bo, C, nullptr, nullptr, 1.0f, MODE_F32,
              blockIdx.y * 128, blockIdx.x * 128, smem);
}

// ---------------------------------------------------------------------------
// Flash attention: S = QK^T in tf32 (single pass), PV in bf16x3.
// CTA = 128 queries of one (b,h); 8 warps; 64-key tiles; 4-stage cp.async
// KV ring; deferred-PV pipeline; log2-domain softmax (ex2).
// ---------------------------------------------------------------------------
constexpr int QFST = 68;                      // f32 row stride (272B)
constexpr int VST  = 72;                      // bf16 row stride (144B)
constexpr int AQ = 0;                         // Q: [128][QFST] f32
constexpr int KVBASE = AQ + 128 * QFST * 4;   // 34816
constexpr int KARR = 64 * QFST * 4;           // 17408 (K fp32)
constexpr int VARR = 64 * VST * 2;            // 9216  (V bf16)
constexpr int KVSTAGE = KARR + 2 * VARR;      // 35840
constexpr int NSTAGE = 4;
constexpr int ATTN_SMEM = KVBASE + NSTAGE * KVSTAGE;   // 178176

__global__ __launch_bounds__(256, 1)
void attn_mma(const float* __restrict__ Qr,
              const float* __restrict__ Kr,
              const __nv_bfloat16* __restrict__ Vh,
              const __nv_bfloat16* __restrict__ Vl,
              float* __restrict__ AO)
{
    extern __shared__ __align__(16) char smem[];
    const uint32_t sb = smem_u32(smem);
    const uint32_t uQ = sb + AQ;

    const int tid  = threadIdx.x;
    const int wid  = tid >> 5;
    const int lane = tid & 31;
    const int bh   = blockIdx.y;
    const int q0   = blockIdx.x * 128;

    const size_t baseQ = ((size_t)bh * SEQ + q0) * DHD;
    const size_t baseK = (size_t)bh * SEQ * DHD;

    auto stage_kv = [&](int st, int kt) {
        uint32_t d = sb + KVBASE + st * KVSTAGE;
        // K fp32: 64x64 f32 = 1024 quads, 4/thread
#pragma unroll
        for (int it = 0; it < 4; it++) {
            int id = tid + it * 256;
            int r = id >> 4, cq = id & 15;
            CPA16(d + (uint32_t)(r * QFST + cq * 4) * 4,
                  Kr + baseK + (size_t)(kt + r) * DHD + cq * 4);
        }
        // V bf16 hi/lo: 2/thread each
        uint32_t dv = d + KARR;
#pragma unroll
        for (int it = 0; it < 2; it++) {
            int id = tid + it * 256;
            int r = id >> 3, c8 = (id & 7) * 8;
            size_t s = baseK + (size_t)(kt + r) * DHD + c8;
            uint32_t o = (uint32_t)(r * VST + c8) * 2;
            CPA16(dv + o,        Vh + s);
            CPA16(dv + VARR + o, Vl + s);
        }
    };

    // Prologue: stage Q (fp32) + tiles 0, 1
#pragma unroll
    for (int it = 0; it < 8; it++) {
        int id = tid + it * 256;              // 0..2047 quads
        int r = id >> 4, cq = id & 15;
        CPA16(uQ + (uint32_t)(r * QFST + cq * 4) * 4,
              Qr + baseQ + (size_t)r * DHD + cq * 4);
    }
    stage_kv(0, 0);
    CP_COMMIT();
    stage_kv(1, 64);
    CP_COMMIT();

    // ldmatrix addressing
    const int qRow = wid * 16 + ((lane >> 3) & 1) * 8 + (lane & 7);
    const int qC   = (lane >> 4) * 4;                    // + ks*8
    const int kRow = ((lane >> 3) & 1) * 8 + (lane & 7); // + nbp*16
    const int kC   = (lane >> 4) * 4;
    const int vRow = ((lane >> 3) & 1) * 8 + (lane & 7); // + ks*16 (b16 trans)
    const int vCol = (lane >> 4) * 8;                    // + nbp*16
    const int gid  = lane >> 2;
    const int tig  = lane & 3;

    float oacc[8][4];
    float m_i[2], l_p[2];
    uint32_t ph[4][4], pl[4][4];
#pragma unroll
    for (int nb = 0; nb < 8; nb++)
#pragma unroll
        for (int q = 0; q < 4; q++) oacc[nb][q] = 0.0f;
    m_i[0] = m_i[1] = -1e30f;
    l_p[0] = l_p[1] = 0.0f;

    auto pv = [&](int st) {
        uint32_t vb = sb + KVBASE + st * KVSTAGE + KARR;
        uint32_t uVH = vb, uVL = vb + VARR;
#pragma unroll
        for (int ks = 0; ks < 4; ks++) {
#pragma unroll
            for (int nbp = 0; nbp < 4; nbp++) {
                uint32_t voff = (uint32_t)((ks * 16 + vRow) * VST +
                                           nbp * 16 + vCol) * 2;
                uint32_t th[4], tl[4];
                ldm4t(th, uVH + voff);
                ldm4t(tl, uVL + voff);
                mma16816(oacc[2 * nbp],     ph[ks], th);
                mma16816(oacc[2 * nbp + 1], ph[ks], th + 2);
                mma16816(oacc[2 * nbp],     ph[ks], tl);
                mma16816(oacc[2 * nbp + 1], ph[ks], tl + 2);
                mma16816(oacc[2 * nbp],     pl[ks], th);
                mma16816(oacc[2 * nbp + 1], pl[ks], th + 2);
            }
        }
    };

    const int NT = SEQ / 64;   // 32
    for (int c = 0; c < NT; c++) {
        __syncthreads();
        if (c + 2 < NT) stage_kv((c + 2) & 3, (c + 2) * 64);
        CP_COMMIT();
        CP_WAIT2();
        __syncthreads();

        const uint32_t uK = sb + KVBASE + (c & 3) * KVSTAGE;

        // ---- S = Q @ K^T (tf32, single pass) ----
        float sacc[8][4];
#pragma unroll
        for (int nb = 0; nb < 8; nb++)
#pragma unroll
            for (int q = 0; q < 4; q++) sacc[nb][q] = 0.0f;

#pragma unroll
        for (int ks = 0; ks < 8; ks++) {       // 8 k8-steps over DH=64
            uint32_t qf[4];
            ldm4(qf, uQ + (uint32_t)(qRow * QFST + ks * 8 + qC) * 4);
#pragma unroll
            for (int nbp = 0; nbp < 4; nbp++) {
                uint32_t kf[4];
                ldm4(kf, uK + (uint32_t)((kRow + nbp * 16) * QFST +
                                         ks * 8 + kC) * 4);
                mma1688(sacc[2 * nbp],     qf, kf[0], kf[2]);
                mma1688(sacc[2 * nbp + 1], qf, kf[1], kf[3]);
            }
        }

        // ---- Deferred PV of previous tile (overlaps softmax) ----
        if (c > 0) pv((c - 1) & 3);

        // ---- Softmax stats (log2 domain) ----
        float sc0, sc1;
#pragma unroll
        for (int hr = 0; hr < 2; hr++) {
            float mloc = -1e30f;
#pragma unroll
            for (int nb = 0; nb < 8; nb++)
                mloc = fmaxf(mloc, fmaxf(sacc[nb][2 * hr], sacc[nb][2 * hr + 1]));
            mloc = fmaxf(mloc, __shfl_xor_sync(0xffffffffu, mloc, 1));
            mloc = fmaxf(mloc, __shfl_xor_sync(0xffffffffu, mloc, 2));
            float mnew = fmaxf(m_i[hr], mloc);
            float sc = ex2(m_i[hr] - mnew);
            m_i[hr] = mnew;
            float psum = 0.0f;
#pragma unroll
            for (int nb = 0; nb < 8; nb++) {
                float p0 = ex2(sacc[nb][2 * hr]     - mnew);
                float p1 = ex2(sacc[nb][2 * hr + 1] - mnew);
                sacc[nb][2 * hr]     = p0;
                sacc[nb][2 * hr + 1] = p1;
                psum += p0 + p1;
            }
            l_p[hr] = l_p[hr] * sc + psum;
            if (hr == 0) sc0 = sc; else sc1 = sc;
        }

        // ---- Rescale O (after PV(c-1) accumulated) ----
#pragma unroll
        for (int nb = 0; nb < 8; nb++) {
            oacc[nb][0] *= sc0; oacc[nb][1] *= sc0;
            oacc[nb][2] *= sc1; oacc[nb][3] *= sc1;
        }

        // ---- Pack P -> bf16 hi/lo fragments for next PV ----
#pragma unroll
        for (int ks = 0; ks < 4; ks++) {
            split2(sacc[2 * ks][0],     sacc[2 * ks][1],     ph[ks][0], pl[ks][0]);
            split2(sacc[2 * ks][2],     sacc[2 * ks][3],     ph[ks][1], pl[ks][1]);
            split2(sacc[2 * ks + 1][0], sacc[2 * ks + 1][1], ph[ks][2], pl[ks][2]);
            split2(sacc[2 * ks + 1][2], sacc[2 * ks + 1][3], ph[ks][3], pl[ks][3]);
        }
    }

    pv((NT - 1) & 3);

    // ---- Final l reduction ----
    float l0 = l_p[0];
    l0 += __shfl_xor_sync(0xffffffffu, l0, 1);
    l0 += __shfl_xor_sync(0xffffffffu, l0, 2);
    float l1 = l_p[1];
    l1 += __shfl_xor_sync(0xffffffffu, l1, 1);
    l1 += __shfl_xor_sync(0xffffffffu, l1, 2);

    // ---- Write normalized, tf32-rounded AO in [B,S,D] layout ----
    const int b = bh >> 4;
    const int h = bh & 15;
#pragma unroll
    for (int hr = 0; hr < 2; hr++) {
        int q = q0 + wid * 16 + gid + hr * 8;
        float inv = 1.0f / (hr ? l1 : l0);
        size_t base = (size_t)(b * SEQ + q) * DM + h * DHD;
#pragma unroll
        for (int nb = 0; nb < 8; nb++) {
            float2 o;
            o.x = totf32(oacc[nb][2 * hr]     * inv);
            o.y = totf32(oacc[nb][2 * hr + 1] * inv);
            *reinterpret_cast<float2*>(&AO[base + nb * 8 + 2 * tig]) = o;
        }
    }
}

// ---------------------------------------------------------------------------
// Launch
// ---------------------------------------------------------------------------
extern "C" void kernel_launch(void* const* d_in, const int* in_sizes, int n_in,
                              void* d_out, int out_size)
{
    const float* x  = (const float*)d_in[0];
    const float* Wq = (const float*)d_in[1];
    const float* bq = (const float*)d_in[2];
    const float* Wk = (const float*)d_in[3];
    const float* bk = (const float*)d_in[4];
    const float* Wv = (const float*)d_in[5];
    const float* bv = (const float*)d_in[6];
    const float* Wo = (const float*)d_in[7];
    const float* bo = (const float*)d_in[8];

    float *xr, *Wtr, *Qr, *Kr, *AO;
    __nv_bfloat16 *Vh, *Vl;
    cudaGetSymbolAddress((void**)&xr,  g_xr);
    cudaGetSymbolAddress((void**)&Wtr, g_Wtr);
    cudaGetSymbolAddress((void**)&Qr,  g_Qr);
    cudaGetSymbolAddress((void**)&Kr,  g_Kr);
    cudaGetSymbolAddress((void**)&Vh,  g_Vh);
    cudaGetSymbolAddress((void**)&Vl,  g_Vl);
    cudaGetSymbolAddress((void**)&AO,  g_AO);

    cudaFuncSetAttribute(gemm_qkv,
                         cudaFuncAttributeMaxDynamicSharedMemorySize, GEMM_SMEM);
    cudaFuncSetAttribute(gemm_o,
                         cudaFuncAttributeMaxDynamicSharedMemorySize, GEMM_SMEM);
    cudaFuncSetAttribute(attn_mma,
                         cudaFuncAttributeMaxDynamicSharedMemorySize, ATTN_SMEM);

    round_x<<<4096, 256>>>(x, xr);
    trans_round_w<<<dim3(1024, 4), 256>>>(Wq, Wk, Wv, Wo, Wtr);

    gemm_qkv<<<dim3(24, 32), 256, GEMM_SMEM>>>(xr, Wtr, bq, bk, bv,
                                               Qr, Kr, Vh, Vl);

    attn_mma<<<dim3(SEQ / 128, BB * HH), 256, ATTN_SMEM>>>(Qr, Kr, Vh, Vl, AO);

    gemm_o<<<dim3(8, 32), 256, GEMM_SMEM>>>(AO, Wtr + 3 * 1048576, bo,
                                            (float*)d_out);
}

// round 12
// speedup vs baseline: 3.4577x; 1.1127x over previous
#include <cuda_runtime.h>
#include <cuda_bf16.h>
#include <math.h>
#include <stdint.h>

// Problem constants
#define BB   2
#define SEQ  2048
#define DM   1024
#define HH   16
#define DHD  64

// Precomputed operands (tf32-rounded fp32) + bf16 hi/lo for V
__device__ float g_xr [4096*1024];
__device__ float g_Wtr[4][1024*1024];           // W^T [n][k], tf32-rounded
__device__ float g_Qr [BB*HH*SEQ*DHD];          // pre-scaled, tf32-rounded
__device__ float g_Kr [BB*HH*SEQ*DHD];
__device__ __nv_bfloat16 g_Vh[BB*HH*SEQ*DHD];
__device__ __nv_bfloat16 g_Vl[BB*HH*SEQ*DHD];
__device__ float g_AO [BB*SEQ*DM];              // tf32-rounded

// ---------------------------------------------------------------------------
// helpers
// ---------------------------------------------------------------------------
__device__ __forceinline__ uint32_t smem_u32(const void* p) {
    uint32_t a;
    asm("{ .reg .u64 t; cvta.to.shared.u64 t, %1; cvt.u32.u64 %0, t; }"
        : "=r"(a) : "l"(p));
    return a;
}
__device__ __forceinline__ void ldm4(uint32_t* r, uint32_t addr) {
    asm volatile("ldmatrix.sync.aligned.m8n8.x4.shared.b16 {%0,%1,%2,%3}, [%4];"
        : "=r"(r[0]), "=r"(r[1]), "=r"(r[2]), "=r"(r[3]) : "r"(addr));
}
__device__ __forceinline__ void ldm4t(uint32_t* r, uint32_t addr) {
    asm volatile("ldmatrix.sync.aligned.m8n8.x4.trans.shared.b16 {%0,%1,%2,%3}, [%4];"
        : "=r"(r[0]), "=r"(r[1]), "=r"(r[2]), "=r"(r[3]) : "r"(addr));
}
// bf16 k16 mma
__device__ __forceinline__ void mma16816(float* c, const uint32_t* a,
                                         const uint32_t* b) {
    asm volatile(
        "mma.sync.aligned.m16n8k16.row.col.f32.bf16.bf16.f32 "
        "{%0,%1,%2,%3}, {%4,%5,%6,%7}, {%8,%9}, {%0,%1,%2,%3};"
        : "+f"(c[0]), "+f"(c[1]), "+f"(c[2]), "+f"(c[3])
        : "r"(a[0]), "r"(a[1]), "r"(a[2]), "r"(a[3]), "r"(b[0]), "r"(b[1]));
}
// tf32 k8 mma
__device__ __forceinline__ void mma1688(float* c, const uint32_t* a,
                                        uint32_t b0, uint32_t b1) {
    asm volatile(
        "mma.sync.aligned.m16n8k8.row.col.f32.tf32.tf32.f32 "
        "{%0,%1,%2,%3}, {%4,%5,%6,%7}, {%8,%9}, {%0,%1,%2,%3};"
        : "+f"(c[0]), "+f"(c[1]), "+f"(c[2]), "+f"(c[3])
        : "r"(a[0]), "r"(a[1]), "r"(a[2]), "r"(a[3]), "r"(b0), "r"(b1));
}
__device__ __forceinline__ float totf32(float x) {
    uint32_t u;
    asm("cvt.rna.tf32.f32 %0, %1;" : "=r"(u) : "f"(x));
    return __uint_as_float(u);
}
__device__ __forceinline__ void split2(float x, float y,
                                       uint32_t& h, uint32_t& l) {
    __nv_bfloat162 hh = __floats2bfloat162_rn(x, y);
    __nv_bfloat162 ll = __floats2bfloat162_rn(x - __bfloat162float(hh.x),
                                              y - __bfloat162float(hh.y));
    h = *reinterpret_cast<uint32_t*>(&hh);
    l = *reinterpret_cast<uint32_t*>(&ll);
}
__device__ __forceinline__ float ex2(float x) {
    float r;
    asm("ex2.approx.ftz.f32 %0, %1;" : "=f"(r) : "f"(x));
    return r;
}

#define CPA16(dst, src) \
    asm volatile("cp.async.cg.shared.global [%0], [%1], 16;" \
                 :: "r"(dst), "l"(src))
#define CP_COMMIT() asm volatile("cp.async.commit_group;" ::: "memory")
#define CP_WAIT1()  asm volatile("cp.async.wait_group 1;" ::: "memory")
#define CP_WAIT0()  asm volatile("cp.async.wait_group 0;" ::: "memory")

// 0.125 * log2(e): folded into Q so attention uses ex2 directly
#define QSCALE 0.18033688011112042f

// ---------------------------------------------------------------------------
// Precompute: round x to tf32
// ---------------------------------------------------------------------------
__global__ __launch_bounds__(256)
void round_x(const float* __restrict__ src, float* __restrict__ dst)
{
    int i = blockIdx.x * 256 + threadIdx.x;
    float4 v = reinterpret_cast<const float4*>(src)[i];
    v.x = totf32(v.x); v.y = totf32(v.y);
    v.z = totf32(v.z); v.w = totf32(v.w);
    reinterpret_cast<float4*>(dst)[i] = v;
}

// Precompute: transpose W [k][n] -> [n][k], round to tf32. grid (1024, 4).
__global__ __launch_bounds__(256)
void trans_round_w(const float* __restrict__ W0,
                   const float* __restrict__ W1,
                   const float* __restrict__ W2,
                   const float* __restrict__ W3,
                   float* __restrict__ out)
{
    __shared__ float t[32][33];
    const float* Ws[4] = {W0, W1, W2, W3};
    const float* W = Ws[blockIdx.y];
    float* dst = out + (size_t)blockIdx.y * 1048576;
    const int tid = threadIdx.x;
    const int n0 = (blockIdx.x & 31) * 32;
    const int k0 = (blockIdx.x >> 5) * 32;
#pragma unroll
    for (int it = 0; it < 4; it++) {
        int id = tid + it * 256;
        int r = id >> 5, c = id & 31;
        t[r][c] = W[(size_t)(k0 + r) * 1024 + n0 + c];
    }
    __syncthreads();
    const int rn = tid >> 3;
    const int c4 = tid & 7;
    float4 o;
    o.x = totf32(t[c4 * 4 + 0][rn]);
    o.y = totf32(t[c4 * 4 + 1][rn]);
    o.z = totf32(t[c4 * 4 + 2][rn]);
    o.w = totf32(t[c4 * 4 + 3][rn]);
    *reinterpret_cast<float4*>(&dst[(size_t)(n0 + rn) * 1024 + k0 + c4 * 4]) = o;
}

// ---------------------------------------------------------------------------
// tf32 GEMM core, cp.async double-buffered. CTA 128x128, BK=32, 8 warps
// (warp tile 64x32). A [m][k], Bt [n][k], both tf32-rounded fp32.
// 2 CTAs/SM (launch_bounds) for latency hiding.
// ---------------------------------------------------------------------------
constexpr int GM = 4096, GN = 1024, GK = 1024;
constexpr int BK = 32;
constexpr int FST = 36;                        // f32 row stride (144B)
constexpr int ARR_F = 128 * FST * 4;           // 18432 B
constexpr int STAGE_B = 2 * ARR_F;             // A + B
constexpr int GEMM_SMEM = 2 * STAGE_B;         // 73728 B

// out modes
#define MODE_F32   0
#define MODE_TF32H 1
#define MODE_BF16H 2

__device__ __forceinline__
void gemm_core(const float* __restrict__ A,
               const float* __restrict__ Bt,
               const float* __restrict__ bias,
               float* __restrict__ Cf,
               __nv_bfloat16* __restrict__ Ch,
               __nv_bfloat16* __restrict__ Cl,
               float scale, int mode,
               int mBase, int nBase, char* smem)
{
    const uint32_t sb = smem_u32(smem);
    const int tid  = threadIdx.x;
    const int wid  = tid >> 5;
    const int lane = tid & 31;
    const int wm   = wid & 1;
    const int wn   = wid >> 1;

    auto stage = [&](int st, int k0) {
        uint32_t d = sb + st * STAGE_B;
#pragma unroll
        for (int it = 0; it < 4; it++) {
            int id = tid + it * 256;          // 0..1023 quads
            int r  = id >> 3;                 // 0..127
            int c  = id & 7;                  // quad within 32 f32
            uint32_t o = (uint32_t)(r * FST + c * 4) * 4;
            CPA16(d + o,          A  + (size_t)(mBase + r) * GK + k0 + c * 4);
            CPA16(d + ARR_F + o,  Bt + (size_t)(nBase + r) * GK + k0 + c * 4);
        }
    };

    float acc[4][4][4];
#pragma unroll
    for (int i = 0; i < 4; i++)
#pragma unroll
        for (int j = 0; j < 4; j++)
#pragma unroll
            for (int q = 0; q < 4; q++) acc[i][j][q] = 0.0f;

    const int aRow = wm * 64 + ((lane >> 3) & 1) * 8 + (lane & 7);
    const int aC   = (lane >> 4) * 4;
    const int bRow = wn * 32 + ((lane >> 3) & 1) * 8 + (lane & 7);
    const int bC   = (lane >> 4) * 4;

    stage(0, 0);
    CP_COMMIT();

    const int NCHUNK = GK / BK;   // 32
    for (int c = 0; c < NCHUNK; c++) {
        if (c + 1 < NCHUNK) {
            stage((c + 1) & 1, (c + 1) * BK);
            CP_COMMIT();
            CP_WAIT1();
        } else {
            CP_WAIT0();
        }
        __syncthreads();

        const uint32_t uA = sb + (c & 1) * STAGE_B;
        const uint32_t uB = uA + ARR_F;

#pragma unroll
        for (int ks = 0; ks < 4; ks++) {
            uint32_t af[4][4];
#pragma unroll
            for (int mb = 0; mb < 4; mb++)
                ldm4(af[mb], uA + (uint32_t)((aRow + mb * 16) * FST +
                                             ks * 8 + aC) * 4);
            uint32_t bf[2][4];
#pragma unroll
            for (int np = 0; np < 2; np++)
                ldm4(bf[np], uB + (uint32_t)((bRow + np * 16) * FST +
                                             ks * 8 + bC) * 4);
#pragma unroll
            for (int mb = 0; mb < 4; mb++) {
                mma1688(acc[mb][0], af[mb], bf[0][0], bf[0][2]);
                mma1688(acc[mb][1], af[mb], bf[0][1], bf[0][3]);
                mma1688(acc[mb][2], af[mb], bf[1][0], bf[1][2]);
                mma1688(acc[mb][3], af[mb], bf[1][1], bf[1][3]);
            }
        }
        __syncthreads();
    }

    const int gid = lane >> 2;
    const int tig = lane & 3;
#pragma unroll
    for (int nb = 0; nb < 4; nb++) {
        int col = nBase + wn * 32 + nb * 8 + 2 * tig;
        float2 bv = *reinterpret_cast<const float2*>(bias + col);
#pragma unroll
        for (int mb = 0; mb < 4; mb++) {
            int row0 = mBase + wm * 64 + mb * 16 + gid;
#pragma unroll
            for (int half = 0; half < 2; half++) {
                int row = row0 + half * 8;
                float ox = (acc[mb][nb][half * 2 + 0] + bv.x) * scale;
                float oy = (acc[mb][nb][half * 2 + 1] + bv.y) * scale;
                if (mode == MODE_F32) {
                    float2 o; o.x = ox; o.y = oy;
                    *reinterpret_cast<float2*>(&Cf[(size_t)row * GN + col]) = o;
                } else {
                    int b = row >> 11, s = row & (SEQ - 1);
                    int h = col >> 6, dh = col & (DHD - 1);
                    size_t idx = (((size_t)(b * HH + h) * SEQ + s) * DHD) + dh;
                    if (mode == MODE_TF32H) {
                        float2 o; o.x = totf32(ox); o.y = totf32(oy);
                        *reinterpret_cast<float2*>(&Cf[idx]) = o;
                    } else {
                        uint32_t hp, lp;
                        split2(ox, oy, hp, lp);
                        *reinterpret_cast<uint32_t*>(&Ch[idx]) = hp;
                        *reinterpret_cast<uint32_t*>(&Cl[idx]) = lp;
                    }
                }
            }
        }
    }
}

// Fused Q/K/V projection: grid (24, 32); blockIdx.x>>3 selects the matrix.
__global__ __launch_bounds__(256, 2)
void gemm_qkv(const float* __restrict__ xr,
              const float* __restrict__ Wtr,
              const float* __restrict__ bq,
              const float* __restrict__ bk,
              const float* __restrict__ bv,
              float* Qr, float* Kr,
              __nv_bfloat16* Vh, __nv_bfloat16* Vl)
{
    extern __shared__ __align__(16) char smem[];
    const int mat = blockIdx.x >> 3;
    const int nBase = (blockIdx.x & 7) * 128;
    const int mBase = blockIdx.y * 128;
    const float* bias = (mat == 0) ? bq : ((mat == 1) ? bk : bv);
    float* Cf = (mat == 0) ? Qr : Kr;
    float scale = (mat == 0) ? QSCALE : 1.0f;
    int mode = (mat == 2) ? MODE_BF16H : MODE_TF32H;
    gemm_core(xr, Wtr + (size_t)mat * 1048576, bias,
              Cf, Vh, Vl, scale, mode, mBase, nBase, smem);
}

// Output projection
__global__ __launch_bounds__(256, 2)
void gemm_o(const float* __restrict__ AO,
            const float* __restrict__ Wtr,
            const float* __restrict__ bo,
            float* __restrict__ C)
{
    extern __shared__ __align__(16) char smem[];
    gemm_core(AO, Wtr, bo, C, nullptr, nullptr, 1.0f, MODE_F32,
              blockIdx.y * 128, blockIdx.x * 128, smem);
}

// ---------------------------------------------------------------------------
// Flash attention: S = QK^T tf32, PV bf16x3. CTA = 128 queries of one (b,h);
// 8 warps; 64-key tiles; 2-stage cp.async KV ring; immediate PV; 2 CTAs/SM.
// ---------------------------------------------------------------------------
constexpr int QFST = 68;                      // f32 row stride
constexpr int VST  = 72;                      // bf16 row stride
constexpr int AQ = 0;                         // Q: [128][QFST] f32
constexpr int KVBASE = AQ + 128 * QFST * 4;   // 34816
constexpr int KARR = 64 * QFST * 4;           // 17408 (K fp32)
constexpr int VARR = 64 * VST * 2;            // 9216  (V bf16)
constexpr int KVSTAGE = KARR + 2 * VARR;      // 35840
constexpr int NSTAGE = 2;
constexpr int ATTN_SMEM = KVBASE + NSTAGE * KVSTAGE;   // 106496

__global__ __launch_bounds__(256, 2)
void attn_mma(const float* __restrict__ Qr,
              const float* __restrict__ Kr,
              const __nv_bfloat16* __restrict__ Vh,
              const __nv_bfloat16* __restrict__ Vl,
              float* __restrict__ AO)
{
    extern __shared__ __align__(16) char smem[];
    const uint32_t sb = smem_u32(smem);
    const uint32_t uQ = sb + AQ;

    const int tid  = threadIdx.x;
    const int wid  = tid >> 5;
    const int lane = tid & 31;
    const int bh   = blockIdx.y;
    const int q0   = blockIdx.x * 128;

    const size_t baseQ = ((size_t)bh * SEQ + q0) * DHD;
    const size_t baseK = (size_t)bh * SEQ * DHD;

    auto stage_kv = [&](int st, int kt) {
        uint32_t d = sb + KVBASE + st * KVSTAGE;
#pragma unroll
        for (int it = 0; it < 4; it++) {
            int id = tid + it * 256;
            int r = id >> 4, cq = id & 15;
            CPA16(d + (uint32_t)(r * QFST + cq * 4) * 4,
                  Kr + baseK + (size_t)(kt + r) * DHD + cq * 4);
        }
        uint32_t dv = d + KARR;
#pragma unroll
        for (int it = 0; it < 2; it++) {
            int id = tid + it * 256;
            int r = id >> 3, c8 = (id & 7) * 8;
            size_t s = baseK + (size_t)(kt + r) * DHD + c8;
            uint32_t o = (uint32_t)(r * VST + c8) * 2;
            CPA16(dv + o,        Vh + s);
            CPA16(dv + VARR + o, Vl + s);
        }
    };

    // Prologue: stage Q + tile 0
#pragma unroll
    for (int it = 0; it < 8; it++) {
        int id = tid + it * 256;
        int r = id >> 4, cq = id & 15;
        CPA16(uQ + (uint32_t)(r * QFST + cq * 4) * 4,
              Qr + baseQ + (size_t)r * DHD + cq * 4);
    }
    stage_kv(0, 0);
    CP_COMMIT();

    // ldmatrix addressing
    const int qRow = wid * 16 + ((lane >> 3) & 1) * 8 + (lane & 7);
    const int qC   = (lane >> 4) * 4;
    const int kRow = ((lane >> 3) & 1) * 8 + (lane & 7);
    const int kC   = (lane >> 4) * 4;
    const int vRow = ((lane >> 3) & 1) * 8 + (lane & 7);
    const int vCol = (lane >> 4) * 8;
    const int gid  = lane >> 2;
    const int tig  = lane & 3;

    float oacc[8][4];
    float m_i[2], l_p[2];
#pragma unroll
    for (int nb = 0; nb < 8; nb++)
#pragma unroll
        for (int q = 0; q < 4; q++) oacc[nb][q] = 0.0f;
    m_i[0] = m_i[1] = -1e30f;
    l_p[0] = l_p[1] = 0.0f;

    const int NT = SEQ / 64;   // 32
    for (int c = 0; c < NT; c++) {
        if (c + 1 < NT) {
            stage_kv((c + 1) & 1, (c + 1) * 64);
            CP_COMMIT();
            CP_WAIT1();
        } else {
            CP_WAIT0();
        }
        __syncthreads();

        const uint32_t uK = sb + KVBASE + (c & 1) * KVSTAGE;
        const uint32_t uVH = uK + KARR, uVL = uVH + VARR;

        // ---- S = Q @ K^T (tf32) ----
        float sacc[8][4];
#pragma unroll
        for (int nb = 0; nb < 8; nb++)
#pragma unroll
            for (int q = 0; q < 4; q++) sacc[nb][q] = 0.0f;

#pragma unroll
        for (int ks = 0; ks < 8; ks++) {
            uint32_t qf[4];
            ldm4(qf, uQ + (uint32_t)(qRow * QFST + ks * 8 + qC) * 4);
#pragma unroll
            for (int nbp = 0; nbp < 4; nbp++) {
                uint32_t kf[4];
                ldm4(kf, uK + (uint32_t)((kRow + nbp * 16) * QFST +
                                         ks * 8 + kC) * 4);
                mma1688(sacc[2 * nbp],     qf, kf[0], kf[2]);
                mma1688(sacc[2 * nbp + 1], qf, kf[1], kf[3]);
            }
        }

        // ---- Softmax (log2 domain) ----
        float sc0, sc1;
#pragma unroll
        for (int hr = 0; hr < 2; hr++) {
            float mloc = -1e30f;
#pragma unroll
            for (int nb = 0; nb < 8; nb++)
                mloc = fmaxf(mloc, fmaxf(sacc[nb][2 * hr], sacc[nb][2 * hr + 1]));
            mloc = fmaxf(mloc, __shfl_xor_sync(0xffffffffu, mloc, 1));
            mloc = fmaxf(mloc, __shfl_xor_sync(0xffffffffu, mloc, 2));
            float mnew = fmaxf(m_i[hr], mloc);
            float sc = ex2(m_i[hr] - mnew);
            m_i[hr] = mnew;
            float psum = 0.0f;
#pragma unroll
            for (int nb = 0; nb < 8; nb++) {
                float p0 = ex2(sacc[nb][2 * hr]     - mnew);
                float p1 = ex2(sacc[nb][2 * hr + 1] - mnew);
                sacc[nb][2 * hr]     = p0;
                sacc[nb][2 * hr + 1] = p1;
                psum += p0 + p1;
            }
            l_p[hr] = l_p[hr] * sc + psum;
            if (hr == 0) sc0 = sc; else sc1 = sc;
        }

        // ---- Rescale O, then immediate PV (P packed per-ks) ----
#pragma unroll
        for (int nb = 0; nb < 8; nb++) {
            oacc[nb][0] *= sc0; oacc[nb][1] *= sc0;
            oacc[nb][2] *= sc1; oacc[nb][3] *= sc1;
        }

#pragma unroll
        for (int ks = 0; ks < 4; ks++) {
            uint32_t phk[4], plk[4];
            split2(sacc[2 * ks][0],     sacc[2 * ks][1],     phk[0], plk[0]);
            split2(sacc[2 * ks][2],     sacc[2 * ks][3],     phk[1], plk[1]);
            split2(sacc[2 * ks + 1][0], sacc[2 * ks + 1][1], phk[2], plk[2]);
            split2(sacc[2 * ks + 1][2], sacc[2 * ks + 1][3], phk[3], plk[3]);
#pragma unroll
            for (int nbp = 0; nbp < 4; nbp++) {
                uint32_t voff = (uint32_t)((ks * 16 + vRow) * VST +
                                           nbp * 16 + vCol) * 2;
                uint32_t th[4], tl[4];
                ldm4t(th, uVH + voff);
                ldm4t(tl, uVL + voff);
                mma16816(oacc[2 * nbp],     phk, th);
                mma16816(oacc[2 * nbp + 1], phk, th + 2);
                mma16816(oacc[2 * nbp],     phk, tl);
                mma16816(oacc[2 * nbp + 1], phk, tl + 2);
                mma16816(oacc[2 * nbp],     plk, th);
                mma16816(oacc[2 * nbp + 1], plk, th + 2);
            }
        }
        __syncthreads();
    }

    // ---- Final l reduction ----
    float l0 = l_p[0];
    l0 += __shfl_xor_sync(0xffffffffu, l0, 1);
    l0 += __shfl_xor_sync(0xffffffffu, l0, 2);
    float l1 = l_p[1];
    l1 += __shfl_xor_sync(0xffffffffu, l1, 1);
    l1 += __shfl_xor_sync(0xffffffffu, l1, 2);

    // ---- Write normalized, tf32-rounded AO in [B,S,D] layout ----
    const int b = bh >> 4;
    const int h = bh & 15;
#pragma unroll
    for (int hr = 0; hr < 2; hr++) {
        int q = q0 + wid * 16 + gid + hr * 8;
        float inv = 1.0f / (hr ? l1 : l0);
        size_t base = (size_t)(b * SEQ + q) * DM + h * DHD;
#pragma unroll
        for (int nb = 0; nb < 8; nb++) {
            float2 o;
            o.x = totf32(oacc[nb][2 * hr]     * inv);
            o.y = totf32(oacc[nb][2 * hr + 1] * inv);
            *reinterpret_cast<float2*>(&AO[base + nb * 8 + 2 * tig]) = o;
        }
    }
}

// ---------------------------------------------------------------------------
// Launch
// ---------------------------------------------------------------------------
extern "C" void kernel_launch(void* const* d_in, const int* in_sizes, int n_in,
                              void* d_out, int out_size)
{
    const float* x  = (const float*)d_in[0];
    const float* Wq = (const float*)d_in[1];
    const float* bq = (const float*)d_in[2];
    const float* Wk = (const float*)d_in[3];
    const float* bk = (const float*)d_in[4];
    const float* Wv = (const float*)d_in[5];
    const float* bv = (const float*)d_in[6];
    const float* Wo = (const float*)d_in[7];
    const float* bo = (const float*)d_in[8];

    float *xr, *Wtr, *Qr, *Kr, *AO;
    __nv_bfloat16 *Vh, *Vl;
    cudaGetSymbolAddress((void**)&xr,  g_xr);
    cudaGetSymbolAddress((void**)&Wtr, g_Wtr);
    cudaGetSymbolAddress((void**)&Qr,  g_Qr);
    cudaGetSymbolAddress((void**)&Kr,  g_Kr);
    cudaGetSymbolAddress((void**)&Vh,  g_Vh);
    cudaGetSymbolAddress((void**)&Vl,  g_Vl);
    cudaGetSymbolAddress((void**)&AO,  g_AO);

    cudaFuncSetAttribute(gemm_qkv,
                         cudaFuncAttributeMaxDynamicSharedMemorySize, GEMM_SMEM);
    cudaFuncSetAttribute(gemm_o,
                         cudaFuncAttributeMaxDynamicSharedMemorySize, GEMM_SMEM);
    cudaFuncSetAttribute(attn_mma,
                         cudaFuncAttributeMaxDynamicSharedMemorySize, ATTN_SMEM);

    round_x<<<4096, 256>>>(x, xr);
    trans_round_w<<<dim3(1024, 4), 256>>>(Wq, Wk, Wv, Wo, Wtr);

    gemm_qkv<<<dim3(24, 32), 256, GEMM_SMEM>>>(xr, Wtr, bq, bk, bv,
                                               Qr, Kr, Vh, Vl);

    attn_mma<<<dim3(SEQ / 128, BB * HH), 256, ATTN_SMEM>>>(Qr, Kr, Vh, Vl, AO);

    gemm_o<<<dim3(8, 32), 256, GEMM_SMEM>>>(AO, Wtr + 3 * 1048576, bo,
                                            (float*)d_out);
}